// round 12
// baseline (speedup 1.0000x reference)
#include <cuda_runtime.h>
#include <math.h>

static const int Bx  = 32;
static const int Nx  = 8192;
static const int Ex  = 256;
static const int NAx = 16;
static const int NPART = 32;           // partials per batch (one per pass1 block)

// output offsets (concatenated outputs, float32)
static const int OFF_OUTS = 0;                       // 32*16*256 = 131072
static const int OFF_INDS = 131072;                  // 512
static const int OFF_W    = 131072 + 512;            // 512
static const int OFF_BC   = 131072 + 1024;           // 8192

// ---- scratch (device globals; no allocation allowed) ----
__device__ float g_r[Ex];                      // combined projection vector (incl. scale)
__device__ float g_logits[Bx * Nx];            // biased attention logits
__device__ float g_partS[Bx * NPART];          // plain exp-sums per block
__device__ float g_partV[Bx * NPART * Ex];     // plain weighted x sums per block (1 MB)
__device__ float g_xa[Bx * NAx * Ex];          // gathered anchor rows + positional enc
__device__ float g_wt[Bx * NAx];               // selected attention weights
__device__ float g_pre[Bx * NAx * Ex];         // pre-LayerNorm anchor outputs (512 KB)
__device__ float g_sinkf;                      // prefetch sink (never actually written)

// packed f32x2 helpers (PTX-only pattern; ptxas never emits FFMA2 from C++)
#define FMA2(d, a, b) \
    asm("fma.rn.f32x2 %0, %1, %2, %0;" : "+l"(d) : "l"(a), "l"(b))
#define ADD2(d, a) \
    asm("add.rn.f32x2 %0, %0, %1;" : "+l"(d) : "l"(a))
#define DUP2(d, s) \
    asm("mov.b64 %0, {%1, %1};" : "=l"(d) : "r"(s))

// ------------------------------------------------------------------
// Kernel 1: r[f] = scale * sum_e Wk[f,e] * (barcode @ Wq)[e]
// ------------------------------------------------------------------
__global__ __launch_bounds__(1024) void k_prep(const float* __restrict__ barcode,
                                               const float* __restrict__ Wq,
                                               const float* __restrict__ Wk) {
    __shared__ float part[4][Ex];
    __shared__ float q[Ex];
    const int t = threadIdx.x, f = t & 255, c = t >> 8;
    const int lane = t & 31, warp = t >> 5;

    float acc = 0.f;
#pragma unroll 8
    for (int j = 0; j < 64; j++) {
        const int ff = c * 64 + j;
        acc += barcode[ff] * Wq[ff * Ex + f];
    }
    part[c][f] = acc;
    __syncthreads();
    if (c == 0) q[f] = part[0][f] + part[1][f] + part[2][f] + part[3][f];
    __syncthreads();

#pragma unroll
    for (int rr = 0; rr < 8; rr++) {
        const int f2 = warp + rr * 32;
        float a = 0.f;
#pragma unroll
        for (int j = 0; j < 8; j++) {
            const int e = lane + j * 32;
            a += Wk[f2 * Ex + e] * q[e];
        }
#pragma unroll
        for (int off = 16; off; off >>= 1) a += __shfl_xor_sync(0xffffffffu, a, off);
        if (lane == 0) g_r[f2] = a * (1.0f / 16.0f);   // scale = 1/sqrt(256)
    }
}

// ------------------------------------------------------------------
// Kernel 2: streaming pass over x (evict-first loads; x read once).
// Coalesced lane-feature map, mask via shfl, logits via register carry.
// Also prefetches w/g into L2 for k_anchor.
// grid: (Nx/256, Bx), block: 256 (8 warps)
// ------------------------------------------------------------------
__global__ __launch_bounds__(256) void k_pass1(const float* __restrict__ x,
                                               const float* __restrict__ mask,
                                               const float* __restrict__ wmat,
                                               const float* __restrict__ gmat) {
    const int b    = blockIdx.y;
    const int warp = threadIdx.x >> 5;
    const int lane = threadIdx.x & 31;
    const int t    = threadIdx.x;

    __shared__ float rs[Ex];
    __shared__ __align__(16) float sv[8 * Ex];   // 8 KB per-warp v partials
    __shared__ float sS[8];

    // L2 prefetch of anchor weights (consumed later by k_anchor).
    {
        const int pid = blockIdx.y * (Nx / 256) + blockIdx.x;   // 0..1023
        const float4 pw = __ldg((const float4*)(wmat + (size_t)pid * 1024) + t);
        const float4 pg = __ldg((const float4*)(gmat + (size_t)pid * 1024) + t);
        const float dummy = pw.x + pw.y + pw.z + pw.w + pg.x + pg.y + pg.z + pg.w;
        if (__float_as_uint(dummy) == 0xdeadbeefu) g_sinkf = dummy;  // never taken
    }

    rs[t] = g_r[t];
    __syncthreads();

    const float r0 = rs[lane * 4 + 0],       r1 = rs[lane * 4 + 1];
    const float r2 = rs[lane * 4 + 2],       r3 = rs[lane * 4 + 3];
    const float r4 = rs[128 + lane * 4 + 0], r5 = rs[128 + lane * 4 + 1];
    const float r6 = rs[128 + lane * 4 + 2], r7 = rs[128 + lane * 4 + 3];

    const int rowbase = blockIdx.x * 256 + warp * 32;
    const float* xb = x + ((size_t)b * Nx + rowbase) * Ex;

    const float mkv = mask[(size_t)b * Nx + rowbase + lane];  // one coalesced load

    float v0 = 0.f, v1 = 0.f, v2 = 0.f, v3 = 0.f;
    float v4 = 0.f, v5 = 0.f, v6 = 0.f, v7 = 0.f;
    float S = 0.f, lrow = 0.f;

#pragma unroll 8
    for (int i = 0; i < 32; i++) {
        const float* row = xb + (size_t)i * Ex;
        const float4 a0 = __ldcs((const float4*)(row + lane * 4));
        const float4 a1 = __ldcs((const float4*)(row + 128 + lane * 4));
        float d = a0.x * r0 + a0.y * r1 + a0.z * r2 + a0.w * r3
                + a1.x * r4 + a1.y * r5 + a1.z * r6 + a1.w * r7;
#pragma unroll
        for (int off = 16; off; off >>= 1) d += __shfl_xor_sync(0xffffffffu, d, off);

        const float mk = __shfl_sync(0xffffffffu, mkv, i);
        const float mm = (mk == -2.0f) ? 0.f : 1.f;
        const float l  = d + (1.f - mm) * (-1e9f);
        if (lane == i) lrow = l;             // carried, stored coalesced after loop

        const float p  = __expf(l);          // masked: exp(-1e9) == 0
        S += p;
        const float pm = p * mm;
        v0 += pm * a0.x;  v1 += pm * a0.y;
        v2 += pm * a0.z;  v3 += pm * a0.w;
        v4 += pm * a1.x;  v5 += pm * a1.y;
        v6 += pm * a1.z;  v7 += pm * a1.w;
    }

    g_logits[(size_t)b * Nx + rowbase + lane] = lrow;   // one coalesced STG per warp

    if (lane == 0) sS[warp] = S;
    {
        float4* pv0 = (float4*)(sv + warp * Ex + lane * 4);
        float4* pv1 = (float4*)(sv + warp * Ex + 128 + lane * 4);
        *pv0 = make_float4(v0, v1, v2, v3);
        *pv1 = make_float4(v4, v5, v6, v7);
    }
    __syncthreads();

    float acc = 0.f;
#pragma unroll
    for (int w2 = 0; w2 < 8; w2++) acc += sv[w2 * Ex + t];
    const int pi = b * NPART + blockIdx.x;
    if (t == 0) {
        float Ssum = 0.f;
#pragma unroll
        for (int w2 = 0; w2 < 8; w2++) Ssum += sS[w2];
        g_partS[pi] = Ssum;
    }
    g_partV[pi * Ex + t] = acc;
}

// ------------------------------------------------------------------
// order-preserving float->u32 map (sentinel 0 = removed; only NaN maps to 0)
// ------------------------------------------------------------------
__device__ __forceinline__ unsigned f2mono(float f) {
    const int b = __float_as_int(f);
    return (unsigned)(b ^ ((b >> 31) | 0x80000000));
}
__device__ __forceinline__ float mono2f(unsigned u) {
    const int b = (u & 0x80000000u) ? (int)(u ^ 0x80000000u) : (int)(~u);
    return __int_as_float(b);
}
__device__ __forceinline__ unsigned long long mk_key(unsigned u, int idx) {
    return ((unsigned long long)u << 32) | (unsigned)(8191 - idx);
}

// ------------------------------------------------------------------
// Kernel 3 (fused combine + select), 512 threads:
//   phase A: all warps fill smem keys + chunk keys
//   phase B/C overlapped: warp 0 greedy selection || warps 1-15
//     combine partials -> sB, reduce Sb (warp 15), named-barrier(480),
//     then GEMV barcode_out = sB @ Wv * (1/Sb)
//   phase D: weights from exact logit bits, gather rows + pos-enc
// grid: Bx, block: 512
// ------------------------------------------------------------------
__global__ __launch_bounds__(512) void k_finish(const float* __restrict__ x,
                                                const float* __restrict__ mask,
                                                const float* __restrict__ Wv,
                                                float* __restrict__ out) {
    const int b = blockIdx.x, tid = threadIdx.x;
    const int lane = tid & 31, warp = tid >> 5;

    __shared__ unsigned sval[Nx];            // 32 KB monotonic logit keys
    __shared__ unsigned long long ckey[256]; // per 32-elem chunk packed key
    __shared__ float    sB[256];             // UN-normalized att@x
    __shared__ float    sSb;
    __shared__ int      s_sel[NAx];
    __shared__ unsigned s_uv[NAx];
    __shared__ unsigned s_u0;

    // ---- phase A: fill + fused chunk-key build ----
    const float4* lg4 = (const float4*)(g_logits + (size_t)b * Nx);
#pragma unroll
    for (int i = 0; i < 4; i++) {
        const int i4 = tid + i * 512;          // float4 index, 0..2047
        const float4 v = lg4[i4];
        const unsigned u0 = f2mono(v.x), u1 = f2mono(v.y);
        const unsigned u2 = f2mono(v.z), u3 = f2mono(v.w);
        ((uint4*)sval)[i4] = make_uint4(u0, u1, u2, u3);
        const int n0 = i4 * 4;
        unsigned long long kk = mk_key(u0, n0);
        unsigned long long k1 = mk_key(u1, n0 + 1);
        unsigned long long k2 = mk_key(u2, n0 + 2);
        unsigned long long k3 = mk_key(u3, n0 + 3);
        k1 = k1 > kk ? k1 : kk;  k3 = k3 > k2 ? k3 : k2;
        kk = k3 > k1 ? k3 : k1;
#pragma unroll
        for (int off = 1; off < 8; off <<= 1) {
            const unsigned long long o = __shfl_xor_sync(0xffffffffu, kk, off);
            kk = o > kk ? o : kk;
        }
        if ((lane & 7) == 0) ckey[i4 >> 3] = kk;
        if (i4 == 0) s_u0 = u0;
    }
    __syncthreads();

    // ---- phase B/C overlapped ----
    if (warp == 0) {
        unsigned long long k[8];
#pragma unroll
        for (int j = 0; j < 8; j++) k[j] = ckey[lane * 8 + j];

        int cnt = 0;
        while (cnt < NAx) {
            unsigned long long m = k[0];
#pragma unroll
            for (int j = 1; j < 8; j++) m = k[j] > m ? k[j] : m;
#pragma unroll
            for (int off = 16; off; off >>= 1) {
                const unsigned long long o = __shfl_xor_sync(0xffffffffu, m, off);
                m = o > m ? o : m;
            }
            if ((unsigned)(m >> 32) == 0u) break;   // all removed

            const int idx = 8191 - (int)(m & 0xFFFFull);
            if (lane == 0) { s_sel[cnt] = idx; s_uv[cnt] = (unsigned)(m >> 32); }
            cnt++;

            const int lo = idx - 2 < 0 ? 0 : idx - 2;
            const int hi = idx + 2 > 8191 ? 8191 : idx + 2;
#pragma unroll
            for (int p0 = 0; p0 < 5; p0++) {
                const int p = lo + p0;
                if (p <= hi && (p >> 8) == lane) sval[p] = 0u;
            }
            __syncwarp();
            const int c0 = lo >> 5, c1 = hi >> 5;
            for (int c = c0; c <= c1; c++) {
                if ((c >> 3) == lane) {
                    unsigned long long kk = 0ull;
                    const uint4* bp = (const uint4*)&sval[c * 32];
#pragma unroll
                    for (int q = 0; q < 8; q++) {
                        const uint4 u = bp[q];
                        const int n = c * 32 + q * 4;
                        unsigned long long a0 = mk_key(u.x, n);
                        unsigned long long a1 = mk_key(u.y, n + 1);
                        unsigned long long a2 = mk_key(u.z, n + 2);
                        unsigned long long a3 = mk_key(u.w, n + 3);
                        a0 = a1 > a0 ? a1 : a0;
                        a2 = a3 > a2 ? a3 : a2;
                        a0 = a2 > a0 ? a2 : a0;
                        kk = a0 > kk ? a0 : kk;
                    }
                    k[c & 7] = kk;
                }
            }
            __syncwarp();
        }

        if (lane == 0) {
            for (int s = cnt; s < NAx; s++) { s_sel[s] = 0; s_uv[s] = s_u0; }
            for (int i = 1; i < NAx; i++) {
                const int ki = s_sel[i]; const unsigned ku = s_uv[i];
                int j = i - 1;
                while (j >= 0 && s_sel[j] > ki) {
                    s_sel[j + 1] = s_sel[j]; s_uv[j + 1] = s_uv[j]; j--;
                }
                s_sel[j + 1] = ki; s_uv[j + 1] = ku;
            }
        }
    } else {
        // warps 1-15: combine partials + Sb + barcode GEMV
        const int f = tid - 32;                      // 0..255 valid for warps 1-8
        if (f < 256) {
            float acc = 0.f;
            const float* pvb = g_partV + (size_t)b * NPART * Ex;
#pragma unroll
            for (int p = 0; p < NPART; p++) acc += pvb[(size_t)p * Ex + f];
            sB[f] = acc;                             // un-normalized
        }
        if (warp == 15) {                            // lane-parallel Sb
            float s = g_partS[b * NPART + lane];
#pragma unroll
            for (int off = 16; off; off >>= 1) s += __shfl_xor_sync(0xffffffffu, s, off);
            if (lane == 0) sSb = s;
        }
        asm volatile("bar.sync 1, 480;" ::: "memory");   // warps 1-15 only

        const float invSb = 1.f / sSb;
        const int c = tid - 32;
        if (c < 256) {
            float o = 0.f;
#pragma unroll 16
            for (int e = 0; e < Ex; e++) o += sB[e] * Wv[e * Ex + c];
            out[OFF_BC + b * Ex + c] = o * invSb;
        }
    }
    __syncthreads();

    // ---- phase D: weights + gather ----
    if (tid < NAx) {
        const int sel = s_sel[tid];
        const float l = mono2f(s_uv[tid]);
        const float mk = mask[(size_t)b * Nx + sel];
        const float mm = (mk == -2.f) ? 0.f : 1.f;
        const float wgt = __expf(l) / sSb * mm;
        out[OFF_INDS + b * NAx + tid] = (float)sel;
        out[OFF_W    + b * NAx + tid] = wgt;
        g_wt[b * NAx + tid] = wgt;
    }
    __syncthreads();

    if (tid < 256) {
        const float inv_dnm = 1.f / powf(40.f, (float)tid * (1.f / 256.f));
#pragma unroll
        for (int a = 0; a < NAx; a++) {
            const int ind = s_sel[a];
            const float xv  = x[((size_t)b * Nx + ind) * Ex + tid];
            const float pos = sinf((float)ind * inv_dnm);
            g_xa[((size_t)b * NAx + a) * Ex + tid] = xv + pos;
        }
    }
}

// ------------------------------------------------------------------
// Kernel 4a: anchor dual GEMM-let, f-split for occupancy + traffic.
// Block = (anchor a, f-quarter fq of 64 f, batch-group bg of 8 b).
// grid (bg*4+fq: 16, a: 16) = 256 blocks x 256 threads (~2/SM).
// L2 weight traffic = 256 x 128KB = 32 MB (halved vs 4-batch layout).
// Thread = half(2: w/g) x ec(8: 32-e chunks) x fg(16 in LOW bits ->
// coalesced 256B x2 warp loads). Per e: LDG.128 + 4 DUP2 + 4 LDS.64 +
// 16 packed FMA2 into acc[fi(4)][bsp(4)]. ec partials via 32KB smem.
// Writes gated/weighted pre-LN g_pre.
// ------------------------------------------------------------------
__global__ __launch_bounds__(256) void k_anchor_mm(const float* __restrict__ wmat,
                                                   const float* __restrict__ gmat) {
    const int fq = blockIdx.x & 3;       // f in [fq*64, fq*64+64)
    const int bg = blockIdx.x >> 2;      // batches [bg*8, bg*8+8)
    const int a  = blockIdx.y;
    const int t  = threadIdx.x;
    const int half = t >> 7;             // 0: w, 1: g
    const int fg   = t & 15;             // 4 f per thread: fq*64 + fg*4 ..
    const int ec   = (t >> 4) & 7;       // e in [ec*32, ec*32+32)

    __shared__ __align__(16) float xs[Ex * 8];         // [e*8 + bs], 8 KB
    __shared__ float wtss[8];
    __shared__ unsigned long long spd[2 * 16 * 4 * 4 * 8]; // 32 KB partials
    __shared__ float ssig[8 * Ex];                      // sigmoid handoff, 8 KB? no:
    // NOTE: ssig not needed; gating resolved directly in finalize from spd.

    for (int idx = t; idx < 8 * Ex; idx += 256) {
        const int bs = idx >> 8, e = idx & 255;
        xs[e * 8 + bs] = g_xa[((size_t)(bg * 8 + bs) * NAx + a) * Ex + e];
    }
    if (t < 8) wtss[t] = g_wt[(bg * 8 + t) * NAx + a];
    __syncthreads();

    unsigned long long acc[16];          // [fi*4 + bsp]
#pragma unroll
    for (int j = 0; j < 16; j++) acc[j] = 0ull;

    const float4* m4 = (const float4*)((half ? gmat : wmat) + (size_t)a * Ex * Ex);
    const int fcol = fq * 16 + fg;       // float4 column
    const int e0 = ec * 32;
#pragma unroll 8
    for (int e2 = 0; e2 < 32; e2++) {
        const int e = e0 + e2;
        const float4 mv = m4[e * 64 + fcol];
        const unsigned long long xp0 = *(const unsigned long long*)&xs[e * 8 + 0];
        const unsigned long long xp1 = *(const unsigned long long*)&xs[e * 8 + 2];
        const unsigned long long xp2 = *(const unsigned long long*)&xs[e * 8 + 4];
        const unsigned long long xp3 = *(const unsigned long long*)&xs[e * 8 + 6];
        unsigned long long d0, d1, d2, d3;
        DUP2(d0, __float_as_uint(mv.x));
        DUP2(d1, __float_as_uint(mv.y));
        DUP2(d2, __float_as_uint(mv.z));
        DUP2(d3, __float_as_uint(mv.w));
        FMA2(acc[0],  xp0, d0); FMA2(acc[1],  xp1, d0);
        FMA2(acc[2],  xp2, d0); FMA2(acc[3],  xp3, d0);
        FMA2(acc[4],  xp0, d1); FMA2(acc[5],  xp1, d1);
        FMA2(acc[6],  xp2, d1); FMA2(acc[7],  xp3, d1);
        FMA2(acc[8],  xp0, d2); FMA2(acc[9],  xp1, d2);
        FMA2(acc[10], xp2, d2); FMA2(acc[11], xp3, d2);
        FMA2(acc[12], xp0, d3); FMA2(acc[13], xp1, d3);
        FMA2(acc[14], xp2, d3); FMA2(acc[15], xp3, d3);
    }

    // store partials: spd[(((half*16+fg)*4+fi)*4+bsp)*8 + ec]
    {
        const int base = (half * 16 + fg) * 16;      // *4*4
#pragma unroll
        for (int j = 0; j < 16; j++)
            spd[(base + j) * 8 + ec] = acc[j];
    }
    __syncthreads();

    // finalize: thread u -> (f_local = u>>2, bsp = u&3) -> 2 outputs
    {
        const int fl  = t >> 2;          // 0..63
        const int bsp = t & 3;           // batch pair
        const int fg2 = fl >> 2, fi = fl & 3;
        const int iw = ((0  + fg2) * 4 + fi) * 4 + bsp;
        const int ig = ((16 + fg2) * 4 + fi) * 4 + bsp;
        unsigned long long sw = spd[iw * 8 + 0];
        unsigned long long sg = spd[ig * 8 + 0];
#pragma unroll
        for (int e2 = 1; e2 < 8; e2++) {
            ADD2(sw, spd[iw * 8 + e2]);
            ADD2(sg, spd[ig * 8 + e2]);
        }
        const float aw0 = __uint_as_float((unsigned)(sw & 0xFFFFFFFFull));
        const float aw1 = __uint_as_float((unsigned)(sw >> 32));
        const float ag0 = __uint_as_float((unsigned)(sg & 0xFFFFFFFFull));
        const float ag1 = __uint_as_float((unsigned)(sg >> 32));
        const int f  = fq * 64 + fl;
        const int b0 = bg * 8 + bsp * 2;
        g_pre[((size_t)b0 * NAx + a) * Ex + f] =
            aw0 / (1.f + __expf(-ag0)) * wtss[bsp * 2];
        g_pre[((size_t)(b0 + 1) * NAx + a) * Ex + f] =
            aw1 / (1.f + __expf(-ag1)) * wtss[bsp * 2 + 1];
    }
}

// ------------------------------------------------------------------
// Kernel 4b: LayerNorm over f for each (b, a). grid 512, block 256.
// ------------------------------------------------------------------
__global__ __launch_bounds__(256) void k_anchor_ln(const float* __restrict__ gamma,
                                                   const float* __restrict__ beta,
                                                   float* __restrict__ out) {
    const int bid = blockIdx.x;          // b*NAx + a
    const int f = threadIdx.x, lane = f & 31, warp = f >> 5;
    __shared__ float rs1[8], rs2[8];

    const float v = g_pre[(size_t)bid * Ex + f];
    float s1 = v, s2 = v * v;
#pragma unroll
    for (int off = 16; off; off >>= 1) {
        s1 += __shfl_xor_sync(0xffffffffu, s1, off);
        s2 += __shfl_xor_sync(0xffffffffu, s2, off);
    }
    if (lane == 0) { rs1[warp] = s1; rs2[warp] = s2; }
    __syncthreads();

    float S = 0.f, Q = 0.f;
#pragma unroll
    for (int w2 = 0; w2 < 8; w2++) { S += rs1[w2]; Q += rs2[w2]; }
    const float mu  = S * (1.f / 256.f);
    const float var = Q * (1.f / 256.f) - mu * mu;
    out[OFF_OUTS + (size_t)bid * Ex + f] =
        (v - mu) * rsqrtf(var + 0.001f) * gamma[f] + beta[f];
}

// ------------------------------------------------------------------
extern "C" void kernel_launch(void* const* d_in, const int* in_sizes, int n_in,
                              void* d_out, int out_size) {
    const float* x       = (const float*)d_in[0];
    const float* mask    = (const float*)d_in[1];
    const float* barcode = (const float*)d_in[2];
    const float* Wq      = (const float*)d_in[3];
    const float* Wk      = (const float*)d_in[4];
    const float* Wv      = (const float*)d_in[5];
    const float* g       = (const float*)d_in[6];
    const float* w       = (const float*)d_in[7];
    const float* ln_g    = (const float*)d_in[8];
    const float* ln_b    = (const float*)d_in[9];
    float* out = (float*)d_out;

    k_prep<<<1, 1024>>>(barcode, Wq, Wk);
    k_pass1<<<dim3(Nx / 256, Bx), 256>>>(x, mask, w, g);
    k_finish<<<Bx, 512>>>(x, mask, Wv, out);
    k_anchor_mm<<<dim3(16, NAx), 256>>>(w, g);
    k_anchor_ln<<<Bx * NAx, 256>>>(ln_g, ln_b, out);
}

// round 13
// speedup vs baseline: 1.0225x; 1.0225x over previous
#include <cuda_runtime.h>
#include <math.h>

static const int Bx  = 32;
static const int Nx  = 8192;
static const int Ex  = 256;
static const int NAx = 16;
static const int NPART = 32;           // partials per batch (one per pass1 block)

// output offsets (concatenated outputs, float32)
static const int OFF_OUTS = 0;                       // 32*16*256 = 131072
static const int OFF_INDS = 131072;                  // 512
static const int OFF_W    = 131072 + 512;            // 512
static const int OFF_BC   = 131072 + 1024;           // 8192

// ---- scratch (device globals; no allocation allowed) ----
__device__ float g_r[Ex];                      // combined projection vector (incl. scale)
__device__ float g_logits[Bx * Nx];            // biased attention logits
__device__ float g_partS[Bx * NPART];          // plain exp-sums per block
__device__ float g_partV[Bx * NPART * Ex];     // plain weighted x sums per block (1 MB)
__device__ float g_xa[Bx * NAx * Ex];          // gathered anchor rows + positional enc
__device__ float g_wt[Bx * NAx];               // selected attention weights
__device__ float g_pre[Bx * NAx * Ex];         // pre-LayerNorm anchor outputs (512 KB)
__device__ float g_sinkf;                      // prefetch sink (never actually written)

// packed f32x2 helpers (PTX-only pattern; ptxas never emits FFMA2 from C++)
#define FMA2(d, a, b) \
    asm("fma.rn.f32x2 %0, %1, %2, %0;" : "+l"(d) : "l"(a), "l"(b))
#define ADD2(d, a) \
    asm("add.rn.f32x2 %0, %0, %1;" : "+l"(d) : "l"(a))
#define DUP2(d, s) \
    asm("mov.b64 %0, {%1, %1};" : "=l"(d) : "r"(s))

// ------------------------------------------------------------------
// Kernel 1: r[f] = scale * sum_e Wk[f,e] * (barcode @ Wq)[e]
// ------------------------------------------------------------------
__global__ __launch_bounds__(1024) void k_prep(const float* __restrict__ barcode,
                                               const float* __restrict__ Wq,
                                               const float* __restrict__ Wk) {
    __shared__ float part[4][Ex];
    __shared__ float q[Ex];
    const int t = threadIdx.x, f = t & 255, c = t >> 8;
    const int lane = t & 31, warp = t >> 5;

    float acc = 0.f;
#pragma unroll 8
    for (int j = 0; j < 64; j++) {
        const int ff = c * 64 + j;
        acc += barcode[ff] * Wq[ff * Ex + f];
    }
    part[c][f] = acc;
    __syncthreads();
    if (c == 0) q[f] = part[0][f] + part[1][f] + part[2][f] + part[3][f];
    __syncthreads();

#pragma unroll
    for (int rr = 0; rr < 8; rr++) {
        const int f2 = warp + rr * 32;
        float a = 0.f;
#pragma unroll
        for (int j = 0; j < 8; j++) {
            const int e = lane + j * 32;
            a += Wk[f2 * Ex + e] * q[e];
        }
#pragma unroll
        for (int off = 16; off; off >>= 1) a += __shfl_xor_sync(0xffffffffu, a, off);
        if (lane == 0) g_r[f2] = a * (1.0f / 16.0f);   // scale = 1/sqrt(256)
    }
}

// ------------------------------------------------------------------
// Kernel 2: streaming pass over x (evict-first loads; x read once).
// Coalesced lane-feature map, mask via shfl, logits via register carry.
// Also prefetches w/g into L2 for k_anchor.
// grid: (Nx/256, Bx), block: 256 (8 warps)
// ------------------------------------------------------------------
__global__ __launch_bounds__(256) void k_pass1(const float* __restrict__ x,
                                               const float* __restrict__ mask,
                                               const float* __restrict__ wmat,
                                               const float* __restrict__ gmat) {
    const int b    = blockIdx.y;
    const int warp = threadIdx.x >> 5;
    const int lane = threadIdx.x & 31;
    const int t    = threadIdx.x;

    __shared__ float rs[Ex];
    __shared__ __align__(16) float sv[8 * Ex];   // 8 KB per-warp v partials
    __shared__ float sS[8];

    // L2 prefetch of anchor weights (consumed later by k_anchor_mm).
    {
        const int pid = blockIdx.y * (Nx / 256) + blockIdx.x;   // 0..1023
        const float4 pw = __ldg((const float4*)(wmat + (size_t)pid * 1024) + t);
        const float4 pg = __ldg((const float4*)(gmat + (size_t)pid * 1024) + t);
        const float dummy = pw.x + pw.y + pw.z + pw.w + pg.x + pg.y + pg.z + pg.w;
        if (__float_as_uint(dummy) == 0xdeadbeefu) g_sinkf = dummy;  // never taken
    }

    rs[t] = g_r[t];
    __syncthreads();

    const float r0 = rs[lane * 4 + 0],       r1 = rs[lane * 4 + 1];
    const float r2 = rs[lane * 4 + 2],       r3 = rs[lane * 4 + 3];
    const float r4 = rs[128 + lane * 4 + 0], r5 = rs[128 + lane * 4 + 1];
    const float r6 = rs[128 + lane * 4 + 2], r7 = rs[128 + lane * 4 + 3];

    const int rowbase = blockIdx.x * 256 + warp * 32;
    const float* xb = x + ((size_t)b * Nx + rowbase) * Ex;

    const float mkv = mask[(size_t)b * Nx + rowbase + lane];  // one coalesced load

    float v0 = 0.f, v1 = 0.f, v2 = 0.f, v3 = 0.f;
    float v4 = 0.f, v5 = 0.f, v6 = 0.f, v7 = 0.f;
    float S = 0.f, lrow = 0.f;

#pragma unroll 8
    for (int i = 0; i < 32; i++) {
        const float* row = xb + (size_t)i * Ex;
        const float4 a0 = __ldcs((const float4*)(row + lane * 4));
        const float4 a1 = __ldcs((const float4*)(row + 128 + lane * 4));
        float d = a0.x * r0 + a0.y * r1 + a0.z * r2 + a0.w * r3
                + a1.x * r4 + a1.y * r5 + a1.z * r6 + a1.w * r7;
#pragma unroll
        for (int off = 16; off; off >>= 1) d += __shfl_xor_sync(0xffffffffu, d, off);

        const float mk = __shfl_sync(0xffffffffu, mkv, i);
        const float mm = (mk == -2.0f) ? 0.f : 1.f;
        const float l  = d + (1.f - mm) * (-1e9f);
        if (lane == i) lrow = l;             // carried, stored coalesced after loop

        const float p  = __expf(l);          // masked: exp(-1e9) == 0
        S += p;
        const float pm = p * mm;
        v0 += pm * a0.x;  v1 += pm * a0.y;
        v2 += pm * a0.z;  v3 += pm * a0.w;
        v4 += pm * a1.x;  v5 += pm * a1.y;
        v6 += pm * a1.z;  v7 += pm * a1.w;
    }

    g_logits[(size_t)b * Nx + rowbase + lane] = lrow;   // one coalesced STG per warp

    if (lane == 0) sS[warp] = S;
    {
        float4* pv0 = (float4*)(sv + warp * Ex + lane * 4);
        float4* pv1 = (float4*)(sv + warp * Ex + 128 + lane * 4);
        *pv0 = make_float4(v0, v1, v2, v3);
        *pv1 = make_float4(v4, v5, v6, v7);
    }
    __syncthreads();

    float acc = 0.f;
#pragma unroll
    for (int w2 = 0; w2 < 8; w2++) acc += sv[w2 * Ex + t];
    const int pi = b * NPART + blockIdx.x;
    if (t == 0) {
        float Ssum = 0.f;
#pragma unroll
        for (int w2 = 0; w2 < 8; w2++) Ssum += sS[w2];
        g_partS[pi] = Ssum;
    }
    g_partV[pi * Ex + t] = acc;
}

// ------------------------------------------------------------------
// order-preserving float->u32 map (sentinel 0 = removed; only NaN maps to 0)
// ------------------------------------------------------------------
__device__ __forceinline__ unsigned f2mono(float f) {
    const int b = __float_as_int(f);
    return (unsigned)(b ^ ((b >> 31) | 0x80000000));
}
__device__ __forceinline__ float mono2f(unsigned u) {
    const int b = (u & 0x80000000u) ? (int)(u ^ 0x80000000u) : (int)(~u);
    return __int_as_float(b);
}
__device__ __forceinline__ unsigned long long mk_key(unsigned u, int idx) {
    return ((unsigned long long)u << 32) | (unsigned)(8191 - idx);
}

// ------------------------------------------------------------------
// Kernel 3 (fused combine + select), 512 threads:
//   phase A: all warps fill smem keys + chunk keys
//   phase B/C overlapped: warp 0 greedy selection || warps 1-15
//     combine partials -> sB, reduce Sb (warp 15), named-barrier(480),
//     then GEMV barcode_out = sB @ Wv * (1/Sb)
//   phase D: weights from exact logit bits, gather rows + pos-enc
// grid: Bx, block: 512
// ------------------------------------------------------------------
__global__ __launch_bounds__(512) void k_finish(const float* __restrict__ x,
                                                const float* __restrict__ mask,
                                                const float* __restrict__ Wv,
                                                float* __restrict__ out) {
    const int b = blockIdx.x, tid = threadIdx.x;
    const int lane = tid & 31, warp = tid >> 5;

    __shared__ unsigned sval[Nx];            // 32 KB monotonic logit keys
    __shared__ unsigned long long ckey[256]; // per 32-elem chunk packed key
    __shared__ float    sB[256];             // UN-normalized att@x
    __shared__ float    sSb;
    __shared__ int      s_sel[NAx];
    __shared__ unsigned s_uv[NAx];
    __shared__ unsigned s_u0;

    // ---- phase A: fill + fused chunk-key build ----
    const float4* lg4 = (const float4*)(g_logits + (size_t)b * Nx);
#pragma unroll
    for (int i = 0; i < 4; i++) {
        const int i4 = tid + i * 512;          // float4 index, 0..2047
        const float4 v = lg4[i4];
        const unsigned u0 = f2mono(v.x), u1 = f2mono(v.y);
        const unsigned u2 = f2mono(v.z), u3 = f2mono(v.w);
        ((uint4*)sval)[i4] = make_uint4(u0, u1, u2, u3);
        const int n0 = i4 * 4;
        unsigned long long kk = mk_key(u0, n0);
        unsigned long long k1 = mk_key(u1, n0 + 1);
        unsigned long long k2 = mk_key(u2, n0 + 2);
        unsigned long long k3 = mk_key(u3, n0 + 3);
        k1 = k1 > kk ? k1 : kk;  k3 = k3 > k2 ? k3 : k2;
        kk = k3 > k1 ? k3 : k1;
#pragma unroll
        for (int off = 1; off < 8; off <<= 1) {
            const unsigned long long o = __shfl_xor_sync(0xffffffffu, kk, off);
            kk = o > kk ? o : kk;
        }
        if ((lane & 7) == 0) ckey[i4 >> 3] = kk;
        if (i4 == 0) s_u0 = u0;
    }
    __syncthreads();

    // ---- phase B/C overlapped ----
    if (warp == 0) {
        unsigned long long k[8];
#pragma unroll
        for (int j = 0; j < 8; j++) k[j] = ckey[lane * 8 + j];

        int cnt = 0;
        while (cnt < NAx) {
            unsigned long long m = k[0];
#pragma unroll
            for (int j = 1; j < 8; j++) m = k[j] > m ? k[j] : m;
#pragma unroll
            for (int off = 16; off; off >>= 1) {
                const unsigned long long o = __shfl_xor_sync(0xffffffffu, m, off);
                m = o > m ? o : m;
            }
            if ((unsigned)(m >> 32) == 0u) break;   // all removed

            const int idx = 8191 - (int)(m & 0xFFFFull);
            if (lane == 0) { s_sel[cnt] = idx; s_uv[cnt] = (unsigned)(m >> 32); }
            cnt++;

            const int lo = idx - 2 < 0 ? 0 : idx - 2;
            const int hi = idx + 2 > 8191 ? 8191 : idx + 2;
#pragma unroll
            for (int p0 = 0; p0 < 5; p0++) {
                const int p = lo + p0;
                if (p <= hi && (p >> 8) == lane) sval[p] = 0u;
            }
            __syncwarp();
            const int c0 = lo >> 5, c1 = hi >> 5;
            for (int c = c0; c <= c1; c++) {
                if ((c >> 3) == lane) {
                    unsigned long long kk = 0ull;
                    const uint4* bp = (const uint4*)&sval[c * 32];
#pragma unroll
                    for (int q = 0; q < 8; q++) {
                        const uint4 u = bp[q];
                        const int n = c * 32 + q * 4;
                        unsigned long long a0 = mk_key(u.x, n);
                        unsigned long long a1 = mk_key(u.y, n + 1);
                        unsigned long long a2 = mk_key(u.z, n + 2);
                        unsigned long long a3 = mk_key(u.w, n + 3);
                        a0 = a1 > a0 ? a1 : a0;
                        a2 = a3 > a2 ? a3 : a2;
                        a0 = a2 > a0 ? a2 : a0;
                        kk = a0 > kk ? a0 : kk;
                    }
                    k[c & 7] = kk;
                }
            }
            __syncwarp();
        }

        if (lane == 0) {
            for (int s = cnt; s < NAx; s++) { s_sel[s] = 0; s_uv[s] = s_u0; }
            for (int i = 1; i < NAx; i++) {
                const int ki = s_sel[i]; const unsigned ku = s_uv[i];
                int j = i - 1;
                while (j >= 0 && s_sel[j] > ki) {
                    s_sel[j + 1] = s_sel[j]; s_uv[j + 1] = s_uv[j]; j--;
                }
                s_sel[j + 1] = ki; s_uv[j + 1] = ku;
            }
        }
    } else {
        // warps 1-15: combine partials + Sb + barcode GEMV
        const int f = tid - 32;                      // 0..255 valid for warps 1-8
        if (f < 256) {
            float acc = 0.f;
            const float* pvb = g_partV + (size_t)b * NPART * Ex;
#pragma unroll
            for (int p = 0; p < NPART; p++) acc += pvb[(size_t)p * Ex + f];
            sB[f] = acc;                             // un-normalized
        }
        if (warp == 15) {                            // lane-parallel Sb
            float s = g_partS[b * NPART + lane];
#pragma unroll
            for (int off = 16; off; off >>= 1) s += __shfl_xor_sync(0xffffffffu, s, off);
            if (lane == 0) sSb = s;
        }
        asm volatile("bar.sync 1, 480;" ::: "memory");   // warps 1-15 only

        const float invSb = 1.f / sSb;
        const int c = tid - 32;
        if (c < 256) {
            float o = 0.f;
#pragma unroll 16
            for (int e = 0; e < Ex; e++) o += sB[e] * Wv[e * Ex + c];
            out[OFF_BC + b * Ex + c] = o * invSb;
        }
    }
    __syncthreads();

    // ---- phase D: weights + gather ----
    if (tid < NAx) {
        const int sel = s_sel[tid];
        const float l = mono2f(s_uv[tid]);
        const float mk = mask[(size_t)b * Nx + sel];
        const float mm = (mk == -2.f) ? 0.f : 1.f;
        const float wgt = __expf(l) / sSb * mm;
        out[OFF_INDS + b * NAx + tid] = (float)sel;
        out[OFF_W    + b * NAx + tid] = wgt;
        g_wt[b * NAx + tid] = wgt;
    }
    __syncthreads();

    if (tid < 256) {
        const float inv_dnm = 1.f / powf(40.f, (float)tid * (1.f / 256.f));
#pragma unroll
        for (int a = 0; a < NAx; a++) {
            const int ind = s_sel[a];
            const float xv  = x[((size_t)b * Nx + ind) * Ex + tid];
            const float pos = sinf((float)ind * inv_dnm);
            g_xa[((size_t)b * NAx + a) * Ex + tid] = xv + pos;
        }
    }
}

// ------------------------------------------------------------------
// Kernel 4a: anchor dual GEMM-let, f-HALF split (proven inner shape).
// Block = (f-half fh: 128 f, batch-group bg: 4 b, anchor a).
// grid (bg*2+fh: 16, a: 16) = 256 blocks x 256 threads, regs ~48 ->
// 3-4 blocks/SM co-resident (vs R9's one 16-warp block), all SMs used.
// Thread = half(2: w/g) x ec(4: 64-e chunks) x fg(32 in LOW 5 bits ->
// full-warp 512B contiguous LDG.128). Same 8 packed-FMA2 accumulators
// as the measured-good R9 loop. L2 weight traffic unchanged (64 MB).
// Writes gated/weighted pre-LN g_pre (LN needs the other f half).
// ------------------------------------------------------------------
__global__ __launch_bounds__(256) void k_anchor_mm(const float* __restrict__ wmat,
                                                   const float* __restrict__ gmat) {
    const int fh = blockIdx.x & 1;       // f in [fh*128, fh*128+128)
    const int bg = blockIdx.x >> 1;      // batches [bg*4, bg*4+4)
    const int a  = blockIdx.y;
    const int t  = threadIdx.x;
    const int fg   = t & 31;             // float4 col within half (low 5 bits)
    const int ec   = (t >> 5) & 3;       // e chunk: [ec*64, ec*64+64)
    const int half = t >> 7;             // 0: w, 1: g

    __shared__ __align__(16) float xs[Ex * 4];         // [e*4+bs], 4 KB
    __shared__ float wts[4];
    __shared__ unsigned long long spd[2 * 32 * 4 * 8]; // 16 KB packed partials

    for (int i = t; i < Ex * 4; i += 256) {
        const int e = i >> 2, bs = i & 3;
        xs[i] = g_xa[((size_t)(bg * 4 + bs) * NAx + a) * Ex + e];
    }
    if (t < 4) wts[t] = g_wt[(bg * 4 + t) * NAx + a];
    __syncthreads();

    // acc[fi*2 + pr]: fi = f within float4 col, pr = batch pair (01 / 23)
    unsigned long long acc[8];
#pragma unroll
    for (int j = 0; j < 8; j++) acc[j] = 0ull;

    const float4* m4 = (const float4*)((half ? gmat : wmat) + (size_t)a * Ex * Ex);
    const int fcol = fh * 32 + fg;
    const int e0 = ec * 64;
#pragma unroll 16
    for (int e2 = 0; e2 < 64; e2++) {
        const int e = e0 + e2;
        const float4 mv = m4[e * 64 + fcol];
        const unsigned long long xp0 = *(const unsigned long long*)&xs[e * 4];
        const unsigned long long xp1 = *(const unsigned long long*)&xs[e * 4 + 2];
        unsigned long long d0, d1, d2, d3;
        DUP2(d0, __float_as_uint(mv.x));
        DUP2(d1, __float_as_uint(mv.y));
        DUP2(d2, __float_as_uint(mv.z));
        DUP2(d3, __float_as_uint(mv.w));
        FMA2(acc[0], xp0, d0);  FMA2(acc[1], xp1, d0);
        FMA2(acc[2], xp0, d1);  FMA2(acc[3], xp1, d1);
        FMA2(acc[4], xp0, d2);  FMA2(acc[5], xp1, d2);
        FMA2(acc[6], xp0, d3);  FMA2(acc[7], xp1, d3);
    }

    // store partials: spd[((half*32+fg)*4 + ec)*8 + j]
    {
        unsigned long long* dst = &spd[(((half << 5) | fg) * 4 + ec) * 8];
#pragma unroll
        for (int j = 0; j < 8; j++) dst[j] = acc[j];
    }
    __syncthreads();

    // finalize: thread -> (fl = t>>1 in 0..127, pr = t&1); 2 outputs
    {
        const int fl = t >> 1, pr = t & 1;
        const int fg2 = fl >> 2, fi = fl & 3;
        const int iw = (((0  | fg2) * 4 + 0) * 8) + fi * 2 + pr;
        const int ig = (((32 | fg2) * 4 + 0) * 8) + fi * 2 + pr;
        unsigned long long sw = spd[iw];
        unsigned long long sg = spd[ig];
#pragma unroll
        for (int e2 = 1; e2 < 4; e2++) {
            ADD2(sw, spd[iw + e2 * 8]);
            ADD2(sg, spd[ig + e2 * 8]);
        }
        const float aw0 = __uint_as_float((unsigned)(sw & 0xFFFFFFFFull));
        const float aw1 = __uint_as_float((unsigned)(sw >> 32));
        const float ag0 = __uint_as_float((unsigned)(sg & 0xFFFFFFFFull));
        const float ag1 = __uint_as_float((unsigned)(sg >> 32));
        const int f  = fh * 128 + fl;
        const int b0 = bg * 4 + pr * 2;
        g_pre[((size_t)b0 * NAx + a) * Ex + f] =
            aw0 / (1.f + __expf(-ag0)) * wts[pr * 2];
        g_pre[((size_t)(b0 + 1) * NAx + a) * Ex + f] =
            aw1 / (1.f + __expf(-ag1)) * wts[pr * 2 + 1];
    }
}

// ------------------------------------------------------------------
// Kernel 4b: LayerNorm over f for each (b, a). grid 512, block 256.
// ------------------------------------------------------------------
__global__ __launch_bounds__(256) void k_anchor_ln(const float* __restrict__ gamma,
                                                   const float* __restrict__ beta,
                                                   float* __restrict__ out) {
    const int bid = blockIdx.x;          // b*NAx + a
    const int f = threadIdx.x, lane = f & 31, warp = f >> 5;
    __shared__ float rs1[8], rs2[8];

    const float v = g_pre[(size_t)bid * Ex + f];
    float s1 = v, s2 = v * v;
#pragma unroll
    for (int off = 16; off; off >>= 1) {
        s1 += __shfl_xor_sync(0xffffffffu, s1, off);
        s2 += __shfl_xor_sync(0xffffffffu, s2, off);
    }
    if (lane == 0) { rs1[warp] = s1; rs2[warp] = s2; }
    __syncthreads();

    float S = 0.f, Q = 0.f;
#pragma unroll
    for (int w2 = 0; w2 < 8; w2++) { S += rs1[w2]; Q += rs2[w2]; }
    const float mu  = S * (1.f / 256.f);
    const float var = Q * (1.f / 256.f) - mu * mu;
    out[OFF_OUTS + (size_t)bid * Ex + f] =
        (v - mu) * rsqrtf(var + 0.001f) * gamma[f] + beta[f];
}

// ------------------------------------------------------------------
extern "C" void kernel_launch(void* const* d_in, const int* in_sizes, int n_in,
                              void* d_out, int out_size) {
    const float* x       = (const float*)d_in[0];
    const float* mask    = (const float*)d_in[1];
    const float* barcode = (const float*)d_in[2];
    const float* Wq      = (const float*)d_in[3];
    const float* Wk      = (const float*)d_in[4];
    const float* Wv      = (const float*)d_in[5];
    const float* g       = (const float*)d_in[6];
    const float* w       = (const float*)d_in[7];
    const float* ln_g    = (const float*)d_in[8];
    const float* ln_b    = (const float*)d_in[9];
    float* out = (float*)d_out;

    k_prep<<<1, 1024>>>(barcode, Wq, Wk);
    k_pass1<<<dim3(Nx / 256, Bx), 256>>>(x, mask, w, g);
    k_finish<<<Bx, 512>>>(x, mask, Wv, out);
    k_anchor_mm<<<dim3(16, NAx), 256>>>(w, g);
    k_anchor_ln<<<Bx * NAx, 256>>>(ln_g, ln_b, out);
}

// round 15
// speedup vs baseline: 1.0678x; 1.0443x over previous
#include <cuda_runtime.h>
#include <math.h>

static const int Bx  = 32;
static const int Nx  = 8192;
static const int Ex  = 256;
static const int NAx = 16;
static const int NPART = 32;           // partials per batch (one per pass1 block)

// output offsets (concatenated outputs, float32)
static const int OFF_OUTS = 0;                       // 32*16*256 = 131072
static const int OFF_INDS = 131072;                  // 512
static const int OFF_W    = 131072 + 512;            // 512
static const int OFF_BC   = 131072 + 1024;           // 8192

// ---- scratch (device globals; no allocation allowed) ----
__device__ float g_r[Ex];                      // combined projection vector (incl. scale)
__device__ float g_logits[Bx * Nx];            // biased attention logits
__device__ float g_partS[Bx * NPART];          // plain exp-sums per block
__device__ float g_partV[Bx * NPART * Ex];     // plain weighted x sums per block (1 MB)
__device__ float g_xa[Bx * NAx * Ex];          // gathered anchor rows + positional enc
__device__ float g_wt[Bx * NAx];               // selected attention weights
__device__ float g_sinkf;                      // prefetch sink (never actually written)

// packed f32x2 helpers (PTX-only pattern; ptxas never emits FFMA2 from C++)
#define FMA2(d, a, b) \
    asm("fma.rn.f32x2 %0, %1, %2, %0;" : "+l"(d) : "l"(a), "l"(b))
#define ADD2(d, a) \
    asm("add.rn.f32x2 %0, %0, %1;" : "+l"(d) : "l"(a))
#define DUP2(d, s) \
    asm("mov.b64 %0, {%1, %1};" : "=l"(d) : "r"(s))

// ------------------------------------------------------------------
// Kernel 1: r[f] = scale * sum_e Wk[f,e] * (barcode @ Wq)[e]
// ------------------------------------------------------------------
__global__ __launch_bounds__(1024) void k_prep(const float* __restrict__ barcode,
                                               const float* __restrict__ Wq,
                                               const float* __restrict__ Wk) {
    __shared__ float part[4][Ex];
    __shared__ float q[Ex];
    const int t = threadIdx.x, f = t & 255, c = t >> 8;
    const int lane = t & 31, warp = t >> 5;

    float acc = 0.f;
#pragma unroll 8
    for (int j = 0; j < 64; j++) {
        const int ff = c * 64 + j;
        acc += barcode[ff] * Wq[ff * Ex + f];
    }
    part[c][f] = acc;
    __syncthreads();
    if (c == 0) q[f] = part[0][f] + part[1][f] + part[2][f] + part[3][f];
    __syncthreads();

#pragma unroll
    for (int rr = 0; rr < 8; rr++) {
        const int f2 = warp + rr * 32;
        float a = 0.f;
#pragma unroll
        for (int j = 0; j < 8; j++) {
            const int e = lane + j * 32;
            a += Wk[f2 * Ex + e] * q[e];
        }
#pragma unroll
        for (int off = 16; off; off >>= 1) a += __shfl_xor_sync(0xffffffffu, a, off);
        if (lane == 0) g_r[f2] = a * (1.0f / 16.0f);   // scale = 1/sqrt(256)
    }
}

// ------------------------------------------------------------------
// Kernel 2: streaming pass over x (evict-first loads; x read once).
// Coalesced lane-feature map, mask via shfl, logits via register carry.
// Also prefetches w/g into L2 for k_anchor.
// grid: (Nx/256, Bx), block: 256 (8 warps)
// ------------------------------------------------------------------
__global__ __launch_bounds__(256) void k_pass1(const float* __restrict__ x,
                                               const float* __restrict__ mask,
                                               const float* __restrict__ wmat,
                                               const float* __restrict__ gmat) {
    const int b    = blockIdx.y;
    const int warp = threadIdx.x >> 5;
    const int lane = threadIdx.x & 31;
    const int t    = threadIdx.x;

    __shared__ float rs[Ex];
    __shared__ __align__(16) float sv[8 * Ex];   // 8 KB per-warp v partials
    __shared__ float sS[8];

    // L2 prefetch of anchor weights (consumed later by k_anchor).
    {
        const int pid = blockIdx.y * (Nx / 256) + blockIdx.x;   // 0..1023
        const float4 pw = __ldg((const float4*)(wmat + (size_t)pid * 1024) + t);
        const float4 pg = __ldg((const float4*)(gmat + (size_t)pid * 1024) + t);
        const float dummy = pw.x + pw.y + pw.z + pw.w + pg.x + pg.y + pg.z + pg.w;
        if (__float_as_uint(dummy) == 0xdeadbeefu) g_sinkf = dummy;  // never taken
    }

    rs[t] = g_r[t];
    __syncthreads();

    const float r0 = rs[lane * 4 + 0],       r1 = rs[lane * 4 + 1];
    const float r2 = rs[lane * 4 + 2],       r3 = rs[lane * 4 + 3];
    const float r4 = rs[128 + lane * 4 + 0], r5 = rs[128 + lane * 4 + 1];
    const float r6 = rs[128 + lane * 4 + 2], r7 = rs[128 + lane * 4 + 3];

    const int rowbase = blockIdx.x * 256 + warp * 32;
    const float* xb = x + ((size_t)b * Nx + rowbase) * Ex;

    const float mkv = mask[(size_t)b * Nx + rowbase + lane];  // one coalesced load

    float v0 = 0.f, v1 = 0.f, v2 = 0.f, v3 = 0.f;
    float v4 = 0.f, v5 = 0.f, v6 = 0.f, v7 = 0.f;
    float S = 0.f, lrow = 0.f;

#pragma unroll 8
    for (int i = 0; i < 32; i++) {
        const float* row = xb + (size_t)i * Ex;
        const float4 a0 = __ldcs((const float4*)(row + lane * 4));
        const float4 a1 = __ldcs((const float4*)(row + 128 + lane * 4));
        float d = a0.x * r0 + a0.y * r1 + a0.z * r2 + a0.w * r3
                + a1.x * r4 + a1.y * r5 + a1.z * r6 + a1.w * r7;
#pragma unroll
        for (int off = 16; off; off >>= 1) d += __shfl_xor_sync(0xffffffffu, d, off);

        const float mk = __shfl_sync(0xffffffffu, mkv, i);
        const float mm = (mk == -2.0f) ? 0.f : 1.f;
        const float l  = d + (1.f - mm) * (-1e9f);
        if (lane == i) lrow = l;             // carried, stored coalesced after loop

        const float p  = __expf(l);          // masked: exp(-1e9) == 0
        S += p;
        const float pm = p * mm;
        v0 += pm * a0.x;  v1 += pm * a0.y;
        v2 += pm * a0.z;  v3 += pm * a0.w;
        v4 += pm * a1.x;  v5 += pm * a1.y;
        v6 += pm * a1.z;  v7 += pm * a1.w;
    }

    g_logits[(size_t)b * Nx + rowbase + lane] = lrow;   // one coalesced STG per warp

    if (lane == 0) sS[warp] = S;
    {
        float4* pv0 = (float4*)(sv + warp * Ex + lane * 4);
        float4* pv1 = (float4*)(sv + warp * Ex + 128 + lane * 4);
        *pv0 = make_float4(v0, v1, v2, v3);
        *pv1 = make_float4(v4, v5, v6, v7);
    }
    __syncthreads();

    float acc = 0.f;
#pragma unroll
    for (int w2 = 0; w2 < 8; w2++) acc += sv[w2 * Ex + t];
    const int pi = b * NPART + blockIdx.x;
    if (t == 0) {
        float Ssum = 0.f;
#pragma unroll
        for (int w2 = 0; w2 < 8; w2++) Ssum += sS[w2];
        g_partS[pi] = Ssum;
    }
    g_partV[pi * Ex + t] = acc;
}

// ------------------------------------------------------------------
// order-preserving float->u32 map (sentinel 0 = removed; only NaN maps to 0)
// ------------------------------------------------------------------
__device__ __forceinline__ unsigned f2mono(float f) {
    const int b = __float_as_int(f);
    return (unsigned)(b ^ ((b >> 31) | 0x80000000));
}
__device__ __forceinline__ float mono2f(unsigned u) {
    const int b = (u & 0x80000000u) ? (int)(u ^ 0x80000000u) : (int)(~u);
    return __int_as_float(b);
}
__device__ __forceinline__ unsigned long long mk_key(unsigned u, int idx) {
    return ((unsigned long long)u << 32) | (unsigned)(8191 - idx);
}

// ------------------------------------------------------------------
// Kernel 3 (fused combine + select), 512 threads:
//   phase A: all warps fill smem keys + chunk keys
//   phase B/C overlapped: warp 0 greedy selection || warps 1-15
//     combine partials -> sB, reduce Sb (warp 15), named-barrier(480),
//     then GEMV barcode_out = sB @ Wv * (1/Sb)
//   phase D: weights from exact logit bits, gather rows + pos-enc
// grid: Bx, block: 512
// ------------------------------------------------------------------
__global__ __launch_bounds__(512) void k_finish(const float* __restrict__ x,
                                                const float* __restrict__ mask,
                                                const float* __restrict__ Wv,
                                                float* __restrict__ out) {
    const int b = blockIdx.x, tid = threadIdx.x;
    const int lane = tid & 31, warp = tid >> 5;

    __shared__ unsigned sval[Nx];            // 32 KB monotonic logit keys
    __shared__ unsigned long long ckey[256]; // per 32-elem chunk packed key
    __shared__ float    sB[256];             // UN-normalized att@x
    __shared__ float    sSb;
    __shared__ int      s_sel[NAx];
    __shared__ unsigned s_uv[NAx];
    __shared__ unsigned s_u0;

    // ---- phase A: fill + fused chunk-key build ----
    const float4* lg4 = (const float4*)(g_logits + (size_t)b * Nx);
#pragma unroll
    for (int i = 0; i < 4; i++) {
        const int i4 = tid + i * 512;          // float4 index, 0..2047
        const float4 v = lg4[i4];
        const unsigned u0 = f2mono(v.x), u1 = f2mono(v.y);
        const unsigned u2 = f2mono(v.z), u3 = f2mono(v.w);
        ((uint4*)sval)[i4] = make_uint4(u0, u1, u2, u3);
        const int n0 = i4 * 4;
        unsigned long long kk = mk_key(u0, n0);
        unsigned long long k1 = mk_key(u1, n0 + 1);
        unsigned long long k2 = mk_key(u2, n0 + 2);
        unsigned long long k3 = mk_key(u3, n0 + 3);
        k1 = k1 > kk ? k1 : kk;  k3 = k3 > k2 ? k3 : k2;
        kk = k3 > k1 ? k3 : k1;
#pragma unroll
        for (int off = 1; off < 8; off <<= 1) {
            const unsigned long long o = __shfl_xor_sync(0xffffffffu, kk, off);
            kk = o > kk ? o : kk;
        }
        if ((lane & 7) == 0) ckey[i4 >> 3] = kk;
        if (i4 == 0) s_u0 = u0;
    }
    __syncthreads();

    // ---- phase B/C overlapped ----
    if (warp == 0) {
        unsigned long long k[8];
#pragma unroll
        for (int j = 0; j < 8; j++) k[j] = ckey[lane * 8 + j];

        int cnt = 0;
        while (cnt < NAx) {
            unsigned long long m = k[0];
#pragma unroll
            for (int j = 1; j < 8; j++) m = k[j] > m ? k[j] : m;
#pragma unroll
            for (int off = 16; off; off >>= 1) {
                const unsigned long long o = __shfl_xor_sync(0xffffffffu, m, off);
                m = o > m ? o : m;
            }
            if ((unsigned)(m >> 32) == 0u) break;   // all removed

            const int idx = 8191 - (int)(m & 0xFFFFull);
            if (lane == 0) { s_sel[cnt] = idx; s_uv[cnt] = (unsigned)(m >> 32); }
            cnt++;

            const int lo = idx - 2 < 0 ? 0 : idx - 2;
            const int hi = idx + 2 > 8191 ? 8191 : idx + 2;
#pragma unroll
            for (int p0 = 0; p0 < 5; p0++) {
                const int p = lo + p0;
                if (p <= hi && (p >> 8) == lane) sval[p] = 0u;
            }
            __syncwarp();
            const int c0 = lo >> 5, c1 = hi >> 5;
            for (int c = c0; c <= c1; c++) {
                if ((c >> 3) == lane) {
                    unsigned long long kk = 0ull;
                    const uint4* bp = (const uint4*)&sval[c * 32];
#pragma unroll
                    for (int q = 0; q < 8; q++) {
                        const uint4 u = bp[q];
                        const int n = c * 32 + q * 4;
                        unsigned long long a0 = mk_key(u.x, n);
                        unsigned long long a1 = mk_key(u.y, n + 1);
                        unsigned long long a2 = mk_key(u.z, n + 2);
                        unsigned long long a3 = mk_key(u.w, n + 3);
                        a0 = a1 > a0 ? a1 : a0;
                        a2 = a3 > a2 ? a3 : a2;
                        a0 = a2 > a0 ? a2 : a0;
                        kk = a0 > kk ? a0 : kk;
                    }
                    k[c & 7] = kk;
                }
            }
            __syncwarp();
        }

        if (lane == 0) {
            for (int s = cnt; s < NAx; s++) { s_sel[s] = 0; s_uv[s] = s_u0; }
            for (int i = 1; i < NAx; i++) {
                const int ki = s_sel[i]; const unsigned ku = s_uv[i];
                int j = i - 1;
                while (j >= 0 && s_sel[j] > ki) {
                    s_sel[j + 1] = s_sel[j]; s_uv[j + 1] = s_uv[j]; j--;
                }
                s_sel[j + 1] = ki; s_uv[j + 1] = ku;
            }
        }
    } else {
        // warps 1-15: combine partials + Sb + barcode GEMV
        const int f = tid - 32;                      // 0..255 valid for warps 1-8
        if (f < 256) {
            float acc = 0.f;
            const float* pvb = g_partV + (size_t)b * NPART * Ex;
#pragma unroll
            for (int p = 0; p < NPART; p++) acc += pvb[(size_t)p * Ex + f];
            sB[f] = acc;                             // un-normalized
        }
        if (warp == 15) {                            // lane-parallel Sb
            float s = g_partS[b * NPART + lane];
#pragma unroll
            for (int off = 16; off; off >>= 1) s += __shfl_xor_sync(0xffffffffu, s, off);
            if (lane == 0) sSb = s;
        }
        asm volatile("bar.sync 1, 480;" ::: "memory");   // warps 1-15 only

        const float invSb = 1.f / sSb;
        const int c = tid - 32;
        if (c < 256) {
            float o = 0.f;
#pragma unroll 16
            for (int e = 0; e < Ex; e++) o += sB[e] * Wv[e * Ex + c];
            out[OFF_BC + b * Ex + c] = o * invSb;
        }
    }
    __syncthreads();

    // ---- phase D: weights + gather ----
    if (tid < NAx) {
        const int sel = s_sel[tid];
        const float l = mono2f(s_uv[tid]);
        const float mk = mask[(size_t)b * Nx + sel];
        const float mm = (mk == -2.f) ? 0.f : 1.f;
        const float wgt = __expf(l) / sSb * mm;
        out[OFF_INDS + b * NAx + tid] = (float)sel;
        out[OFF_W    + b * NAx + tid] = wgt;
        g_wt[b * NAx + tid] = wgt;
    }
    __syncthreads();

    if (tid < 256) {
        const float inv_dnm = 1.f / powf(40.f, (float)tid * (1.f / 256.f));
#pragma unroll
        for (int a = 0; a < NAx; a++) {
            const int ind = s_sel[a];
            const float xv  = x[((size_t)b * Nx + ind) * Ex + tid];
            const float pos = sinf((float)ind * inv_dnm);
            g_xa[((size_t)b * NAx + a) * Ex + tid] = xv + pos;
        }
    }
}

// ------------------------------------------------------------------
// Kernel 4: per-anchor dual GEMM-let over 4 batches per block (R9/R11
// form). 512 threads = half(2) x ec(4: 64-e chunks) x fgroup(64 low
// bits -> warp-contiguous 512B loads). Inner unroll 32: 32 LDG.128 in
// flight to cover ~250-cyc L2 latency. Partials via 32KB smem.
// grid: (8, 16), block: 512
// ------------------------------------------------------------------
__global__ __launch_bounds__(512) void k_anchor(const float* __restrict__ wmat,
                                                const float* __restrict__ gmat,
                                                const float* __restrict__ gamma,
                                                const float* __restrict__ beta,
                                                float* __restrict__ out) {
    const int a  = blockIdx.y;
    const int b0 = blockIdx.x * 4;
    const int t  = threadIdx.x;

    const int half = t >> 8;             // 0: w matrix, 1: g matrix
    const int fg   = t & 63;             // f-group: covers f = fg*4 .. fg*4+3
    const int ec   = (t >> 6) & 3;       // e-chunk: e = ec*64 .. ec*64+63

    __shared__ __align__(16) float xs[Ex * 4];       // [e*4+bs], 4 KB
    __shared__ float wts[4];
    __shared__ unsigned long long spd[2 * 64 * 4 * 8]; // 32 KB packed partials
    __shared__ float rsum[8][4], rsq[8][4];

    for (int i = t; i < Ex * 4; i += 512) {
        const int e = i >> 2, bs = i & 3;
        xs[i] = g_xa[((size_t)(b0 + bs) * NAx + a) * Ex + e];
    }
    if (t < 4) wts[t] = g_wt[(b0 + t) * NAx + a];
    __syncthreads();

    // acc[fi*2 + pr]: fi = f within group (0..3), pr = batch pair (01 / 23)
    unsigned long long acc[8];
#pragma unroll
    for (int j = 0; j < 8; j++) acc[j] = 0ull;

    const float4* m4 = (const float4*)((half ? gmat : wmat) + (size_t)a * Ex * Ex);
    const int e0 = ec * 64;
#pragma unroll 32
    for (int e2 = 0; e2 < 64; e2++) {
        const int e = e0 + e2;
        const float4 mv = m4[e * 64 + fg];
        const unsigned long long xp0 = *(const unsigned long long*)&xs[e * 4];
        const unsigned long long xp1 = *(const unsigned long long*)&xs[e * 4 + 2];
        unsigned long long d0, d1, d2, d3;
        DUP2(d0, __float_as_uint(mv.x));
        DUP2(d1, __float_as_uint(mv.y));
        DUP2(d2, __float_as_uint(mv.z));
        DUP2(d3, __float_as_uint(mv.w));
        FMA2(acc[0], xp0, d0);  FMA2(acc[1], xp1, d0);
        FMA2(acc[2], xp0, d1);  FMA2(acc[3], xp1, d1);
        FMA2(acc[4], xp0, d2);  FMA2(acc[5], xp1, d2);
        FMA2(acc[6], xp0, d3);  FMA2(acc[7], xp1, d3);
    }

    // store packed partials: [(half*64+fg)*4 + ec]*8 + j
    {
        unsigned long long* dst = &spd[(((half << 6) | fg) * 4 + ec) * 8];
#pragma unroll
        for (int j = 0; j < 8; j++) dst[j] = acc[j];
    }
    __syncthreads();

    // finalize on threads 0..255 (thread = output feature f)
    const int f = t & 255;
    const int lane = t & 31, warp = t >> 5;
    float aw[4], ag[4], pre[4];
    if (t < 256) {
        const int fg2 = f >> 2, fi = f & 3;
#pragma unroll
        for (int h = 0; h < 2; h++) {
#pragma unroll
            for (int pr = 0; pr < 2; pr++) {
                const unsigned long long* src =
                    &spd[((h << 6) | fg2) * 4 * 8 + fi * 2 + pr];
                unsigned long long s = src[0];
                ADD2(s, src[8]);
                ADD2(s, src[16]);
                ADD2(s, src[24]);
                const float lo2 = __uint_as_float((unsigned)(s & 0xFFFFFFFFull));
                const float hi2 = __uint_as_float((unsigned)(s >> 32));
                if (h == 0) { aw[pr * 2] = lo2; aw[pr * 2 + 1] = hi2; }
                else        { ag[pr * 2] = lo2; ag[pr * 2 + 1] = hi2; }
            }
        }
#pragma unroll
        for (int bs = 0; bs < 4; bs++)
            pre[bs] = aw[bs] / (1.f + __expf(-ag[bs])) * wts[bs];
#pragma unroll
        for (int bs = 0; bs < 4; bs++) {
            float s1 = pre[bs], s2 = pre[bs] * pre[bs];
#pragma unroll
            for (int off = 16; off; off >>= 1) {
                s1 += __shfl_xor_sync(0xffffffffu, s1, off);
                s2 += __shfl_xor_sync(0xffffffffu, s2, off);
            }
            if (lane == 0) { rsum[warp][bs] = s1; rsq[warp][bs] = s2; }
        }
    }
    __syncthreads();

    if (t < 256) {
        const float gam = gamma[f], bet = beta[f];
#pragma unroll
        for (int bs = 0; bs < 4; bs++) {
            float S = 0.f, Q = 0.f;
#pragma unroll
            for (int w2 = 0; w2 < 8; w2++) { S += rsum[w2][bs]; Q += rsq[w2][bs]; }
            const float mu  = S * (1.f / 256.f);
            const float var = Q * (1.f / 256.f) - mu * mu;
            out[((size_t)(b0 + bs) * NAx + a) * Ex + f] =
                (pre[bs] - mu) * rsqrtf(var + 0.001f) * gam + bet;
        }
    }
}

// ------------------------------------------------------------------
extern "C" void kernel_launch(void* const* d_in, const int* in_sizes, int n_in,
                              void* d_out, int out_size) {
    const float* x       = (const float*)d_in[0];
    const float* mask    = (const float*)d_in[1];
    const float* barcode = (const float*)d_in[2];
    const float* Wq      = (const float*)d_in[3];
    const float* Wk      = (const float*)d_in[4];
    const float* Wv      = (const float*)d_in[5];
    const float* g       = (const float*)d_in[6];
    const float* w       = (const float*)d_in[7];
    const float* ln_g    = (const float*)d_in[8];
    const float* ln_b    = (const float*)d_in[9];
    float* out = (float*)d_out;

    k_prep<<<1, 1024>>>(barcode, Wq, Wk);
    k_pass1<<<dim3(Nx / 256, Bx), 256>>>(x, mask, w, g);
    k_finish<<<Bx, 512>>>(x, mask, Wv, out);
    k_anchor<<<dim3(8, NAx), 512>>>(w, g, ln_g, ln_b, out);
}

// round 16
// speedup vs baseline: 1.0910x; 1.0217x over previous
#include <cuda_runtime.h>
#include <math.h>

static const int Bx  = 32;
static const int Nx  = 8192;
static const int Ex  = 256;
static const int NAx = 16;
static const int NPART = 32;           // partials per batch (one per pass1 block)

// output offsets (concatenated outputs, float32)
static const int OFF_OUTS = 0;                       // 32*16*256 = 131072
static const int OFF_INDS = 131072;                  // 512
static const int OFF_W    = 131072 + 512;            // 512
static const int OFF_BC   = 131072 + 1024;           // 8192

// ---- scratch (device globals; no allocation allowed) ----
__device__ float g_r[Ex];                      // combined projection vector (incl. scale)
__device__ float g_logits[Bx * Nx];            // biased attention logits
__device__ float g_partS[Bx * NPART];          // plain exp-sums per block
__device__ float g_partV[Bx * NPART * Ex];     // plain weighted x sums per block (1 MB)
__device__ float g_xa[Bx * NAx * Ex];          // gathered anchor rows + positional enc
__device__ float g_wt[Bx * NAx];               // selected attention weights
__device__ int   g_flag[Bx];                   // per-batch done flags (finish -> anchor)
__device__ float g_sinkf;                      // prefetch sink (never actually written)

// packed f32x2 helpers (PTX-only pattern; ptxas never emits FFMA2 from C++)
#define FMA2(d, a, b) \
    asm("fma.rn.f32x2 %0, %1, %2, %0;" : "+l"(d) : "l"(a), "l"(b))
#define ADD2(d, a) \
    asm("add.rn.f32x2 %0, %0, %1;" : "+l"(d) : "l"(a))
#define DUP2(d, s) \
    asm("mov.b64 %0, {%1, %1};" : "=l"(d) : "r"(s))

// ------------------------------------------------------------------
// Kernel 1: r[f] = scale * sum_e Wk[f,e] * (barcode @ Wq)[e]
// ------------------------------------------------------------------
__global__ __launch_bounds__(1024) void k_prep(const float* __restrict__ barcode,
                                               const float* __restrict__ Wq,
                                               const float* __restrict__ Wk) {
    __shared__ float part[4][Ex];
    __shared__ float q[Ex];
    const int t = threadIdx.x, f = t & 255, c = t >> 8;
    const int lane = t & 31, warp = t >> 5;

    float acc = 0.f;
#pragma unroll 8
    for (int j = 0; j < 64; j++) {
        const int ff = c * 64 + j;
        acc += barcode[ff] * Wq[ff * Ex + f];
    }
    part[c][f] = acc;
    __syncthreads();
    if (c == 0) q[f] = part[0][f] + part[1][f] + part[2][f] + part[3][f];
    __syncthreads();

#pragma unroll
    for (int rr = 0; rr < 8; rr++) {
        const int f2 = warp + rr * 32;
        float a = 0.f;
#pragma unroll
        for (int j = 0; j < 8; j++) {
            const int e = lane + j * 32;
            a += Wk[f2 * Ex + e] * q[e];
        }
#pragma unroll
        for (int off = 16; off; off >>= 1) a += __shfl_xor_sync(0xffffffffu, a, off);
        if (lane == 0) g_r[f2] = a * (1.0f / 16.0f);   // scale = 1/sqrt(256)
    }
}

// ------------------------------------------------------------------
// Kernel 2: streaming pass over x (evict-first loads; x read once).
// Also zeroes the tail-kernel flags (block (0,0)).
// grid: (Nx/256, Bx), block: 256 (8 warps)
// ------------------------------------------------------------------
__global__ __launch_bounds__(256) void k_pass1(const float* __restrict__ x,
                                               const float* __restrict__ mask) {
    const int b    = blockIdx.y;
    const int warp = threadIdx.x >> 5;
    const int lane = threadIdx.x & 31;
    const int t    = threadIdx.x;

    __shared__ float rs[Ex];
    __shared__ __align__(16) float sv[8 * Ex];   // 8 KB per-warp v partials
    __shared__ float sS[8];

    if (blockIdx.x == 0 && blockIdx.y == 0 && t < Bx) g_flag[t] = 0;

    rs[t] = g_r[t];
    __syncthreads();

    const float r0 = rs[lane * 4 + 0],       r1 = rs[lane * 4 + 1];
    const float r2 = rs[lane * 4 + 2],       r3 = rs[lane * 4 + 3];
    const float r4 = rs[128 + lane * 4 + 0], r5 = rs[128 + lane * 4 + 1];
    const float r6 = rs[128 + lane * 4 + 2], r7 = rs[128 + lane * 4 + 3];

    const int rowbase = blockIdx.x * 256 + warp * 32;
    const float* xb = x + ((size_t)b * Nx + rowbase) * Ex;

    const float mkv = mask[(size_t)b * Nx + rowbase + lane];  // one coalesced load

    float v0 = 0.f, v1 = 0.f, v2 = 0.f, v3 = 0.f;
    float v4 = 0.f, v5 = 0.f, v6 = 0.f, v7 = 0.f;
    float S = 0.f, lrow = 0.f;

#pragma unroll 8
    for (int i = 0; i < 32; i++) {
        const float* row = xb + (size_t)i * Ex;
        const float4 a0 = __ldcs((const float4*)(row + lane * 4));
        const float4 a1 = __ldcs((const float4*)(row + 128 + lane * 4));
        float d = a0.x * r0 + a0.y * r1 + a0.z * r2 + a0.w * r3
                + a1.x * r4 + a1.y * r5 + a1.z * r6 + a1.w * r7;
#pragma unroll
        for (int off = 16; off; off >>= 1) d += __shfl_xor_sync(0xffffffffu, d, off);

        const float mk = __shfl_sync(0xffffffffu, mkv, i);
        const float mm = (mk == -2.0f) ? 0.f : 1.f;
        const float l  = d + (1.f - mm) * (-1e9f);
        if (lane == i) lrow = l;             // carried, stored coalesced after loop

        const float p  = __expf(l);          // masked: exp(-1e9) == 0
        S += p;
        const float pm = p * mm;
        v0 += pm * a0.x;  v1 += pm * a0.y;
        v2 += pm * a0.z;  v3 += pm * a0.w;
        v4 += pm * a1.x;  v5 += pm * a1.y;
        v6 += pm * a1.z;  v7 += pm * a1.w;
    }

    g_logits[(size_t)b * Nx + rowbase + lane] = lrow;   // one coalesced STG per warp

    if (lane == 0) sS[warp] = S;
    {
        float4* pv0 = (float4*)(sv + warp * Ex + lane * 4);
        float4* pv1 = (float4*)(sv + warp * Ex + 128 + lane * 4);
        *pv0 = make_float4(v0, v1, v2, v3);
        *pv1 = make_float4(v4, v5, v6, v7);
    }
    __syncthreads();

    float acc = 0.f;
#pragma unroll
    for (int w2 = 0; w2 < 8; w2++) acc += sv[w2 * Ex + t];
    const int pi = b * NPART + blockIdx.x;
    if (t == 0) {
        float Ssum = 0.f;
#pragma unroll
        for (int w2 = 0; w2 < 8; w2++) Ssum += sS[w2];
        g_partS[pi] = Ssum;
    }
    g_partV[pi * Ex + t] = acc;
}

// ------------------------------------------------------------------
// order-preserving float->u32 map (sentinel 0 = removed; only NaN maps to 0)
// ------------------------------------------------------------------
__device__ __forceinline__ unsigned f2mono(float f) {
    const int b = __float_as_int(f);
    return (unsigned)(b ^ ((b >> 31) | 0x80000000));
}
__device__ __forceinline__ float mono2f(unsigned u) {
    const int b = (u & 0x80000000u) ? (int)(u ^ 0x80000000u) : (int)(~u);
    return __int_as_float(b);
}
__device__ __forceinline__ unsigned long long mk_key(unsigned u, int idx) {
    return ((unsigned long long)u << 32) | (unsigned)(8191 - idx);
}

// ------------------------------------------------------------------
// Shared-memory overlays for the fused tail kernel (union keeps static
// smem at max(36.3KB) < 48KB).
// ------------------------------------------------------------------
struct FinishS {
    unsigned sval[Nx];             // 32 KB monotonic logit keys
    unsigned long long ckey[256];  // per 32-elem chunk packed key
    float    sB[256];
    float    sSb;
    int      s_sel[NAx];
    unsigned s_uv[NAx];
    unsigned s_u0;
};
struct AnchorS {
    float xs[Ex * 4];
    float wts[4];
    unsigned long long spd[2 * 64 * 4 * 8];   // 32 KB packed partials
    float rsum[8][4], rsq[8][4];
};
union TailS { FinishS fin; AnchorS anc; };

// ------------------------------------------------------------------
// Kernel 3 (FUSED tail): grid 160 x 512.
//  blocks 0..31   : finish role (combine+select+gather for batch b),
//                   then publishes g_flag[b].
//  blocks 32..159 : anchor role (bg,a). Stripe-prefetches w/g into L2
//                   (overlaps finish), spin-waits on its 4 batch flags,
//                   then runs the R11 dual GEMM-let + LayerNorm.
// All 32 producer blocks are in wave 1 (160 blocks / 148 SMs) -> no
// deadlock. Flags zeroed by k_pass1 each replay.
// ------------------------------------------------------------------
__global__ __launch_bounds__(512) void k_tail(const float* __restrict__ x,
                                              const float* __restrict__ mask,
                                              const float* __restrict__ Wv,
                                              const float* __restrict__ wmat,
                                              const float* __restrict__ gmat,
                                              const float* __restrict__ gamma,
                                              const float* __restrict__ beta,
                                              float* __restrict__ out) {
    __shared__ TailS ts;
    const int tid = threadIdx.x;
    const int lane = tid & 31, warp = tid >> 5;

    if (blockIdx.x < 32) {
        // ================= FINISH ROLE =================
        const int b = blockIdx.x;

        // ---- phase A: fill + fused chunk-key build ----
        const float4* lg4 = (const float4*)(g_logits + (size_t)b * Nx);
#pragma unroll
        for (int i = 0; i < 4; i++) {
            const int i4 = tid + i * 512;          // float4 index, 0..2047
            const float4 v = lg4[i4];
            const unsigned u0 = f2mono(v.x), u1 = f2mono(v.y);
            const unsigned u2 = f2mono(v.z), u3 = f2mono(v.w);
            ((uint4*)ts.fin.sval)[i4] = make_uint4(u0, u1, u2, u3);
            const int n0 = i4 * 4;
            unsigned long long kk = mk_key(u0, n0);
            unsigned long long k1 = mk_key(u1, n0 + 1);
            unsigned long long k2 = mk_key(u2, n0 + 2);
            unsigned long long k3 = mk_key(u3, n0 + 3);
            k1 = k1 > kk ? k1 : kk;  k3 = k3 > k2 ? k3 : k2;
            kk = k3 > k1 ? k3 : k1;
#pragma unroll
            for (int off = 1; off < 8; off <<= 1) {
                const unsigned long long o = __shfl_xor_sync(0xffffffffu, kk, off);
                kk = o > kk ? o : kk;
            }
            if ((lane & 7) == 0) ts.fin.ckey[i4 >> 3] = kk;
            if (i4 == 0) ts.fin.s_u0 = u0;
        }
        __syncthreads();

        // ---- phase B/C overlapped ----
        if (warp == 0) {
            unsigned long long k[8];
#pragma unroll
            for (int j = 0; j < 8; j++) k[j] = ts.fin.ckey[lane * 8 + j];

            int cnt = 0;
            while (cnt < NAx) {
                unsigned long long m = k[0];
#pragma unroll
                for (int j = 1; j < 8; j++) m = k[j] > m ? k[j] : m;
#pragma unroll
                for (int off = 16; off; off >>= 1) {
                    const unsigned long long o = __shfl_xor_sync(0xffffffffu, m, off);
                    m = o > m ? o : m;
                }
                if ((unsigned)(m >> 32) == 0u) break;   // all removed

                const int idx = 8191 - (int)(m & 0xFFFFull);
                if (lane == 0) { ts.fin.s_sel[cnt] = idx; ts.fin.s_uv[cnt] = (unsigned)(m >> 32); }
                cnt++;

                const int lo = idx - 2 < 0 ? 0 : idx - 2;
                const int hi = idx + 2 > 8191 ? 8191 : idx + 2;
#pragma unroll
                for (int p0 = 0; p0 < 5; p0++) {
                    const int p = lo + p0;
                    if (p <= hi && (p >> 8) == lane) ts.fin.sval[p] = 0u;
                }
                __syncwarp();
                const int c0 = lo >> 5, c1 = hi >> 5;
                for (int c = c0; c <= c1; c++) {
                    if ((c >> 3) == lane) {
                        unsigned long long kk = 0ull;
                        const uint4* bp = (const uint4*)&ts.fin.sval[c * 32];
#pragma unroll
                        for (int q = 0; q < 8; q++) {
                            const uint4 u = bp[q];
                            const int n = c * 32 + q * 4;
                            unsigned long long a0 = mk_key(u.x, n);
                            unsigned long long a1 = mk_key(u.y, n + 1);
                            unsigned long long a2 = mk_key(u.z, n + 2);
                            unsigned long long a3 = mk_key(u.w, n + 3);
                            a0 = a1 > a0 ? a1 : a0;
                            a2 = a3 > a2 ? a3 : a2;
                            a0 = a2 > a0 ? a2 : a0;
                            kk = a0 > kk ? a0 : kk;
                        }
                        k[c & 7] = kk;
                    }
                }
                __syncwarp();
            }

            if (lane == 0) {
                for (int s = cnt; s < NAx; s++) { ts.fin.s_sel[s] = 0; ts.fin.s_uv[s] = ts.fin.s_u0; }
                for (int i = 1; i < NAx; i++) {
                    const int ki = ts.fin.s_sel[i]; const unsigned ku = ts.fin.s_uv[i];
                    int j = i - 1;
                    while (j >= 0 && ts.fin.s_sel[j] > ki) {
                        ts.fin.s_sel[j + 1] = ts.fin.s_sel[j]; ts.fin.s_uv[j + 1] = ts.fin.s_uv[j]; j--;
                    }
                    ts.fin.s_sel[j + 1] = ki; ts.fin.s_uv[j + 1] = ku;
                }
            }
        } else {
            // warps 1-15: combine partials + Sb + barcode GEMV
            const int f = tid - 32;
            if (f < 256) {
                float acc = 0.f;
                const float* pvb = g_partV + (size_t)b * NPART * Ex;
#pragma unroll
                for (int p = 0; p < NPART; p++) acc += pvb[(size_t)p * Ex + f];
                ts.fin.sB[f] = acc;                  // un-normalized
            }
            if (warp == 15) {                        // lane-parallel Sb
                float s = g_partS[b * NPART + lane];
#pragma unroll
                for (int off = 16; off; off >>= 1) s += __shfl_xor_sync(0xffffffffu, s, off);
                if (lane == 0) ts.fin.sSb = s;
            }
            asm volatile("bar.sync 1, 480;" ::: "memory");   // warps 1-15 only

            const float invSb = 1.f / ts.fin.sSb;
            const int c = tid - 32;
            if (c < 256) {
                float o = 0.f;
#pragma unroll 16
                for (int e = 0; e < Ex; e++) o += ts.fin.sB[e] * Wv[e * Ex + c];
                out[OFF_BC + b * Ex + c] = o * invSb;
            }
        }
        __syncthreads();

        // ---- phase D: weights + gather ----
        if (tid < NAx) {
            const int sel = ts.fin.s_sel[tid];
            const float l = mono2f(ts.fin.s_uv[tid]);
            const float mk = mask[(size_t)b * Nx + sel];
            const float mm = (mk == -2.f) ? 0.f : 1.f;
            const float wgt = __expf(l) / ts.fin.sSb * mm;
            out[OFF_INDS + b * NAx + tid] = (float)sel;
            out[OFF_W    + b * NAx + tid] = wgt;
            g_wt[b * NAx + tid] = wgt;
        }
        __syncthreads();

        if (tid < 256) {
            const float inv_dnm = 1.f / powf(40.f, (float)tid * (1.f / 256.f));
#pragma unroll
            for (int a = 0; a < NAx; a++) {
                const int ind = ts.fin.s_sel[a];
                const float xv  = x[((size_t)b * Nx + ind) * Ex + tid];
                const float pos = sinf((float)ind * inv_dnm);
                g_xa[((size_t)b * NAx + a) * Ex + tid] = xv + pos;
            }
        }

        // ---- publish ----
        __threadfence();
        __syncthreads();
        if (tid == 0) atomicExch(&g_flag[b], 1);

    } else {
        // ================= ANCHOR ROLE =================
        const int idx = blockIdx.x - 32;     // 0..127
        const int bg  = idx & 7;             // batch group
        const int a   = idx >> 3;            // anchor
        const int b0  = bg * 4;
        const int t   = tid;

        const int half = t >> 8;             // 0: w matrix, 1: g matrix
        const int fg   = t & 63;             // f-group: f = fg*4 .. fg*4+3
        const int ec   = (t >> 6) & 3;       // e-chunk: e = ec*64 .. ec*64+63

        // stripe-prefetch w/g into L2 (overlaps the finish blocks)
        {
            const float4* wp4 = (const float4*)wmat + (size_t)idx * 2048;
            const float4* gp4 = (const float4*)gmat + (size_t)idx * 2048;
            float sink = 0.f;
#pragma unroll
            for (int i = 0; i < 4; i++) {
                const float4 pa = __ldg(wp4 + t + i * 512);
                const float4 pb = __ldg(gp4 + t + i * 512);
                sink += pa.x + pa.y + pa.z + pa.w + pb.x + pb.y + pb.z + pb.w;
            }
            if (__float_as_uint(sink) == 0xdeadbeefu) g_sinkf = sink;  // never taken
        }

        // wait for the 4 producer batches
        if (t == 0) {
#pragma unroll
            for (int i = 0; i < 4; i++)
                while (atomicAdd(&g_flag[b0 + i], 0) == 0) { __nanosleep(64); }
            __threadfence();
        }
        __syncthreads();

        for (int i = t; i < Ex * 4; i += 512) {
            const int e = i >> 2, bs = i & 3;
            ts.anc.xs[i] = __ldcg(&g_xa[((size_t)(b0 + bs) * NAx + a) * Ex + e]);
        }
        if (t < 4) ts.anc.wts[t] = __ldcg(&g_wt[(b0 + t) * NAx + a]);
        __syncthreads();

        unsigned long long acc[8];
#pragma unroll
        for (int j = 0; j < 8; j++) acc[j] = 0ull;

        const float4* m4 = (const float4*)((half ? gmat : wmat) + (size_t)a * Ex * Ex);
        const int e0 = ec * 64;
#pragma unroll 16
        for (int e2 = 0; e2 < 64; e2++) {
            const int e = e0 + e2;
            const float4 mv = m4[e * 64 + fg];
            const unsigned long long xp0 = *(const unsigned long long*)&ts.anc.xs[e * 4];
            const unsigned long long xp1 = *(const unsigned long long*)&ts.anc.xs[e * 4 + 2];
            unsigned long long d0, d1, d2, d3;
            DUP2(d0, __float_as_uint(mv.x));
            DUP2(d1, __float_as_uint(mv.y));
            DUP2(d2, __float_as_uint(mv.z));
            DUP2(d3, __float_as_uint(mv.w));
            FMA2(acc[0], xp0, d0);  FMA2(acc[1], xp1, d0);
            FMA2(acc[2], xp0, d1);  FMA2(acc[3], xp1, d1);
            FMA2(acc[4], xp0, d2);  FMA2(acc[5], xp1, d2);
            FMA2(acc[6], xp0, d3);  FMA2(acc[7], xp1, d3);
        }

        {
            unsigned long long* dst = &ts.anc.spd[(((half << 6) | fg) * 4 + ec) * 8];
#pragma unroll
            for (int j = 0; j < 8; j++) dst[j] = acc[j];
        }
        __syncthreads();

        const int f = t & 255;
        float aw[4], ag[4], pre[4];
        if (t < 256) {
            const int fg2 = f >> 2, fi = f & 3;
#pragma unroll
            for (int h = 0; h < 2; h++) {
#pragma unroll
                for (int pr = 0; pr < 2; pr++) {
                    const unsigned long long* src =
                        &ts.anc.spd[((h << 6) | fg2) * 4 * 8 + fi * 2 + pr];
                    unsigned long long s = src[0];
                    ADD2(s, src[8]);
                    ADD2(s, src[16]);
                    ADD2(s, src[24]);
                    const float lo2 = __uint_as_float((unsigned)(s & 0xFFFFFFFFull));
                    const float hi2 = __uint_as_float((unsigned)(s >> 32));
                    if (h == 0) { aw[pr * 2] = lo2; aw[pr * 2 + 1] = hi2; }
                    else        { ag[pr * 2] = lo2; ag[pr * 2 + 1] = hi2; }
                }
            }
#pragma unroll
            for (int bs = 0; bs < 4; bs++)
                pre[bs] = aw[bs] / (1.f + __expf(-ag[bs])) * ts.anc.wts[bs];
#pragma unroll
            for (int bs = 0; bs < 4; bs++) {
                float s1 = pre[bs], s2 = pre[bs] * pre[bs];
#pragma unroll
                for (int off = 16; off; off >>= 1) {
                    s1 += __shfl_xor_sync(0xffffffffu, s1, off);
                    s2 += __shfl_xor_sync(0xffffffffu, s2, off);
                }
                if (lane == 0) { ts.anc.rsum[warp][bs] = s1; ts.anc.rsq[warp][bs] = s2; }
            }
        }
        __syncthreads();

        if (t < 256) {
            const float gam = gamma[f], bet = beta[f];
#pragma unroll
            for (int bs = 0; bs < 4; bs++) {
                float S = 0.f, Q = 0.f;
#pragma unroll
                for (int w2 = 0; w2 < 8; w2++) { S += ts.anc.rsum[w2][bs]; Q += ts.anc.rsq[w2][bs]; }
                const float mu  = S * (1.f / 256.f);
                const float var = Q * (1.f / 256.f) - mu * mu;
                out[((size_t)(b0 + bs) * NAx + a) * Ex + f] =
                    (pre[bs] - mu) * rsqrtf(var + 0.001f) * gam + bet;
            }
        }
    }
}

// ------------------------------------------------------------------
extern "C" void kernel_launch(void* const* d_in, const int* in_sizes, int n_in,
                              void* d_out, int out_size) {
    const float* x       = (const float*)d_in[0];
    const float* mask    = (const float*)d_in[1];
    const float* barcode = (const float*)d_in[2];
    const float* Wq      = (const float*)d_in[3];
    const float* Wk      = (const float*)d_in[4];
    const float* Wv      = (const float*)d_in[5];
    const float* g       = (const float*)d_in[6];
    const float* w       = (const float*)d_in[7];
    const float* ln_g    = (const float*)d_in[8];
    const float* ln_b    = (const float*)d_in[9];
    float* out = (float*)d_out;

    k_prep<<<1, 1024>>>(barcode, Wq, Wk);
    k_pass1<<<dim3(Nx / 256, Bx), 256>>>(x, mask);
    k_tail<<<160, 512>>>(x, mask, Wv, w, g, ln_g, ln_b, out);
}

// round 17
// speedup vs baseline: 1.1232x; 1.0295x over previous
#include <cuda_runtime.h>
#include <math.h>

static const int Bx  = 32;
static const int Nx  = 8192;
static const int Ex  = 256;
static const int NAx = 16;
static const int NPART = 32;           // partials per batch (one per pass1 block)

// output offsets (concatenated outputs, float32)
static const int OFF_OUTS = 0;                       // 32*16*256 = 131072
static const int OFF_INDS = 131072;                  // 512
static const int OFF_W    = 131072 + 512;            // 512
static const int OFF_BC   = 131072 + 1024;           // 8192

// ---- scratch (device globals; no allocation allowed) ----
__device__ float g_qpart[64 * Ex];             // barcode@Wq partials (64 KB)
__device__ float g_r[Ex];                      // combined projection vector (incl. scale)
__device__ float g_logits[Bx * Nx];            // biased attention logits
__device__ float g_partS[Bx * NPART];          // plain exp-sums per block
__device__ float g_partV[Bx * NPART * Ex];     // plain weighted x sums per block (1 MB)
__device__ float g_xa[Bx * NAx * Ex];          // gathered anchor rows + positional enc
__device__ float g_wt[Bx * NAx];               // selected attention weights
__device__ int   g_flag[Bx];                   // per-batch done flags (finish -> anchor)
__device__ float g_sinkf;                      // prefetch sink (never actually written)

// packed f32x2 helpers (PTX-only pattern; ptxas never emits FFMA2 from C++)
#define FMA2(d, a, b) \
    asm("fma.rn.f32x2 %0, %1, %2, %0;" : "+l"(d) : "l"(a), "l"(b))
#define ADD2(d, a) \
    asm("add.rn.f32x2 %0, %0, %1;" : "+l"(d) : "l"(a))
#define DUP2(d, s) \
    asm("mov.b64 %0, {%1, %1};" : "=l"(d) : "r"(s))

// ------------------------------------------------------------------
// Kernel 0a: q partials. Block p: q_p[e] = sum_{f in [4p,4p+4)}
// barcode[f] * Wq[f,e].  grid 64 x 256 -> Wq pulled chip-wide.
// ------------------------------------------------------------------
__global__ __launch_bounds__(256) void k_prep1(const float* __restrict__ barcode,
                                               const float* __restrict__ Wq) {
    const int p = blockIdx.x, t = threadIdx.x;
    const int f0 = p * 4;
    float acc = 0.f;
#pragma unroll
    for (int j = 0; j < 4; j++)
        acc += barcode[f0 + j] * Wq[(f0 + j) * Ex + t];
    g_qpart[p * Ex + t] = acc;
}

// ------------------------------------------------------------------
// Kernel 0b: r[f2] = scale * Wk[f2,:] . q, q = sum of 64 partials.
// grid 32 x 256 (8 warps; warp handles one row f2 = blk*8 + warp).
// ------------------------------------------------------------------
__global__ __launch_bounds__(256) void k_prep2(const float* __restrict__ Wk) {
    __shared__ float q[Ex];
    const int t = threadIdx.x, lane = t & 31, warp = t >> 5;

    float s = 0.f;
#pragma unroll
    for (int p = 0; p < 64; p++) s += g_qpart[p * Ex + t];
    q[t] = s;
    __syncthreads();

    const int f2 = blockIdx.x * 8 + warp;
    float a = 0.f;
#pragma unroll
    for (int j = 0; j < 8; j++) {
        const int e = lane + j * 32;
        a += Wk[f2 * Ex + e] * q[e];
    }
#pragma unroll
    for (int off = 16; off; off >>= 1) a += __shfl_xor_sync(0xffffffffu, a, off);
    if (lane == 0) g_r[f2] = a * (1.0f / 16.0f);   // scale = 1/sqrt(256)
}

// ------------------------------------------------------------------
// Kernel 2: streaming pass over x (evict-first loads; x read once).
// Also zeroes the tail-kernel flags (block (0,0)).
// grid: (Nx/256, Bx), block: 256 (8 warps)
// ------------------------------------------------------------------
__global__ __launch_bounds__(256) void k_pass1(const float* __restrict__ x,
                                               const float* __restrict__ mask) {
    const int b    = blockIdx.y;
    const int warp = threadIdx.x >> 5;
    const int lane = threadIdx.x & 31;
    const int t    = threadIdx.x;

    __shared__ float rs[Ex];
    __shared__ __align__(16) float sv[8 * Ex];   // 8 KB per-warp v partials
    __shared__ float sS[8];

    if (blockIdx.x == 0 && blockIdx.y == 0 && t < Bx) g_flag[t] = 0;

    rs[t] = g_r[t];
    __syncthreads();

    const float r0 = rs[lane * 4 + 0],       r1 = rs[lane * 4 + 1];
    const float r2 = rs[lane * 4 + 2],       r3 = rs[lane * 4 + 3];
    const float r4 = rs[128 + lane * 4 + 0], r5 = rs[128 + lane * 4 + 1];
    const float r6 = rs[128 + lane * 4 + 2], r7 = rs[128 + lane * 4 + 3];

    const int rowbase = blockIdx.x * 256 + warp * 32;
    const float* xb = x + ((size_t)b * Nx + rowbase) * Ex;

    const float mkv = mask[(size_t)b * Nx + rowbase + lane];  // one coalesced load

    float v0 = 0.f, v1 = 0.f, v2 = 0.f, v3 = 0.f;
    float v4 = 0.f, v5 = 0.f, v6 = 0.f, v7 = 0.f;
    float S = 0.f, lrow = 0.f;

#pragma unroll 8
    for (int i = 0; i < 32; i++) {
        const float* row = xb + (size_t)i * Ex;
        const float4 a0 = __ldcs((const float4*)(row + lane * 4));
        const float4 a1 = __ldcs((const float4*)(row + 128 + lane * 4));
        float d = a0.x * r0 + a0.y * r1 + a0.z * r2 + a0.w * r3
                + a1.x * r4 + a1.y * r5 + a1.z * r6 + a1.w * r7;
#pragma unroll
        for (int off = 16; off; off >>= 1) d += __shfl_xor_sync(0xffffffffu, d, off);

        const float mk = __shfl_sync(0xffffffffu, mkv, i);
        const float mm = (mk == -2.0f) ? 0.f : 1.f;
        const float l  = d + (1.f - mm) * (-1e9f);
        if (lane == i) lrow = l;             // carried, stored coalesced after loop

        const float p  = __expf(l);          // masked: exp(-1e9) == 0
        S += p;
        const float pm = p * mm;
        v0 += pm * a0.x;  v1 += pm * a0.y;
        v2 += pm * a0.z;  v3 += pm * a0.w;
        v4 += pm * a1.x;  v5 += pm * a1.y;
        v6 += pm * a1.z;  v7 += pm * a1.w;
    }

    g_logits[(size_t)b * Nx + rowbase + lane] = lrow;   // one coalesced STG per warp

    if (lane == 0) sS[warp] = S;
    {
        float4* pv0 = (float4*)(sv + warp * Ex + lane * 4);
        float4* pv1 = (float4*)(sv + warp * Ex + 128 + lane * 4);
        *pv0 = make_float4(v0, v1, v2, v3);
        *pv1 = make_float4(v4, v5, v6, v7);
    }
    __syncthreads();

    float acc = 0.f;
#pragma unroll
    for (int w2 = 0; w2 < 8; w2++) acc += sv[w2 * Ex + t];
    const int pi = b * NPART + blockIdx.x;
    if (t == 0) {
        float Ssum = 0.f;
#pragma unroll
        for (int w2 = 0; w2 < 8; w2++) Ssum += sS[w2];
        g_partS[pi] = Ssum;
    }
    g_partV[pi * Ex + t] = acc;
}

// ------------------------------------------------------------------
// order-preserving float->u32 map (sentinel 0 = removed; only NaN maps to 0)
// ------------------------------------------------------------------
__device__ __forceinline__ unsigned f2mono(float f) {
    const int b = __float_as_int(f);
    return (unsigned)(b ^ ((b >> 31) | 0x80000000));
}
__device__ __forceinline__ float mono2f(unsigned u) {
    const int b = (u & 0x80000000u) ? (int)(u ^ 0x80000000u) : (int)(~u);
    return __int_as_float(b);
}
__device__ __forceinline__ unsigned long long mk_key(unsigned u, int idx) {
    return ((unsigned long long)u << 32) | (unsigned)(8191 - idx);
}

// ------------------------------------------------------------------
// Shared-memory overlays for the fused tail kernel (union keeps static
// smem at max(36.3KB) < 48KB).
// ------------------------------------------------------------------
struct FinishS {
    unsigned sval[Nx];             // 32 KB monotonic logit keys
    unsigned long long ckey[256];  // per 32-elem chunk packed key
    float    sB[256];
    float    sSb;
    int      s_sel[NAx];
    unsigned s_uv[NAx];
    unsigned s_u0;
};
struct AnchorS {
    float xs[Ex * 4];
    float wts[4];
    unsigned long long spd[2 * 64 * 4 * 8];   // 32 KB packed partials
    float rsum[8][4], rsq[8][4];
};
union TailS { FinishS fin; AnchorS anc; };

// ------------------------------------------------------------------
// Kernel 3 (FUSED tail): grid 160 x 512.
//  blocks 0..31   : finish role (combine+select+gather for batch b),
//                   then publishes g_flag[b].
//  blocks 32..159 : anchor role (bg,a). Stripe-prefetches w/g into L2
//                   (overlaps finish), spin-waits on its 4 batch flags,
//                   then runs the R11 dual GEMM-let + LayerNorm.
// All 32 producer blocks are in wave 1 (160 blocks / 148 SMs) -> no
// deadlock. Flags zeroed by k_pass1 each replay.
// ------------------------------------------------------------------
__global__ __launch_bounds__(512) void k_tail(const float* __restrict__ x,
                                              const float* __restrict__ mask,
                                              const float* __restrict__ Wv,
                                              const float* __restrict__ wmat,
                                              const float* __restrict__ gmat,
                                              const float* __restrict__ gamma,
                                              const float* __restrict__ beta,
                                              float* __restrict__ out) {
    __shared__ TailS ts;
    const int tid = threadIdx.x;
    const int lane = tid & 31, warp = tid >> 5;

    if (blockIdx.x < 32) {
        // ================= FINISH ROLE =================
        const int b = blockIdx.x;

        // ---- phase A: fill + fused chunk-key build ----
        const float4* lg4 = (const float4*)(g_logits + (size_t)b * Nx);
#pragma unroll
        for (int i = 0; i < 4; i++) {
            const int i4 = tid + i * 512;          // float4 index, 0..2047
            const float4 v = lg4[i4];
            const unsigned u0 = f2mono(v.x), u1 = f2mono(v.y);
            const unsigned u2 = f2mono(v.z), u3 = f2mono(v.w);
            ((uint4*)ts.fin.sval)[i4] = make_uint4(u0, u1, u2, u3);
            const int n0 = i4 * 4;
            unsigned long long kk = mk_key(u0, n0);
            unsigned long long k1 = mk_key(u1, n0 + 1);
            unsigned long long k2 = mk_key(u2, n0 + 2);
            unsigned long long k3 = mk_key(u3, n0 + 3);
            k1 = k1 > kk ? k1 : kk;  k3 = k3 > k2 ? k3 : k2;
            kk = k3 > k1 ? k3 : k1;
#pragma unroll
            for (int off = 1; off < 8; off <<= 1) {
                const unsigned long long o = __shfl_xor_sync(0xffffffffu, kk, off);
                kk = o > kk ? o : kk;
            }
            if ((lane & 7) == 0) ts.fin.ckey[i4 >> 3] = kk;
            if (i4 == 0) ts.fin.s_u0 = u0;
        }
        __syncthreads();

        // ---- phase B/C overlapped ----
        if (warp == 0) {
            unsigned long long k[8];
#pragma unroll
            for (int j = 0; j < 8; j++) k[j] = ts.fin.ckey[lane * 8 + j];

            int cnt = 0;
            while (cnt < NAx) {
                unsigned long long m = k[0];
#pragma unroll
                for (int j = 1; j < 8; j++) m = k[j] > m ? k[j] : m;
#pragma unroll
                for (int off = 16; off; off >>= 1) {
                    const unsigned long long o = __shfl_xor_sync(0xffffffffu, m, off);
                    m = o > m ? o : m;
                }
                if ((unsigned)(m >> 32) == 0u) break;   // all removed

                const int idx = 8191 - (int)(m & 0xFFFFull);
                if (lane == 0) { ts.fin.s_sel[cnt] = idx; ts.fin.s_uv[cnt] = (unsigned)(m >> 32); }
                cnt++;

                const int lo = idx - 2 < 0 ? 0 : idx - 2;
                const int hi = idx + 2 > 8191 ? 8191 : idx + 2;
#pragma unroll
                for (int p0 = 0; p0 < 5; p0++) {
                    const int p = lo + p0;
                    if (p <= hi && (p >> 8) == lane) ts.fin.sval[p] = 0u;
                }
                __syncwarp();
                const int c0 = lo >> 5, c1 = hi >> 5;
                for (int c = c0; c <= c1; c++) {
                    if ((c >> 3) == lane) {
                        unsigned long long kk = 0ull;
                        const uint4* bp = (const uint4*)&ts.fin.sval[c * 32];
#pragma unroll
                        for (int q = 0; q < 8; q++) {
                            const uint4 u = bp[q];
                            const int n = c * 32 + q * 4;
                            unsigned long long a0 = mk_key(u.x, n);
                            unsigned long long a1 = mk_key(u.y, n + 1);
                            unsigned long long a2 = mk_key(u.z, n + 2);
                            unsigned long long a3 = mk_key(u.w, n + 3);
                            a0 = a1 > a0 ? a1 : a0;
                            a2 = a3 > a2 ? a3 : a2;
                            a0 = a2 > a0 ? a2 : a0;
                            kk = a0 > kk ? a0 : kk;
                        }
                        k[c & 7] = kk;
                    }
                }
                __syncwarp();
            }

            if (lane == 0) {
                for (int s = cnt; s < NAx; s++) { ts.fin.s_sel[s] = 0; ts.fin.s_uv[s] = ts.fin.s_u0; }
                for (int i = 1; i < NAx; i++) {
                    const int ki = ts.fin.s_sel[i]; const unsigned ku = ts.fin.s_uv[i];
                    int j = i - 1;
                    while (j >= 0 && ts.fin.s_sel[j] > ki) {
                        ts.fin.s_sel[j + 1] = ts.fin.s_sel[j]; ts.fin.s_uv[j + 1] = ts.fin.s_uv[j]; j--;
                    }
                    ts.fin.s_sel[j + 1] = ki; ts.fin.s_uv[j + 1] = ku;
                }
            }
        } else {
            // warps 1-15: combine partials + Sb + barcode GEMV
            const int f = tid - 32;
            if (f < 256) {
                float acc = 0.f;
                const float* pvb = g_partV + (size_t)b * NPART * Ex;
#pragma unroll
                for (int p = 0; p < NPART; p++) acc += pvb[(size_t)p * Ex + f];
                ts.fin.sB[f] = acc;                  // un-normalized
            }
            if (warp == 15) {                        // lane-parallel Sb
                float s = g_partS[b * NPART + lane];
#pragma unroll
                for (int off = 16; off; off >>= 1) s += __shfl_xor_sync(0xffffffffu, s, off);
                if (lane == 0) ts.fin.sSb = s;
            }
            asm volatile("bar.sync 1, 480;" ::: "memory");   // warps 1-15 only

            const float invSb = 1.f / ts.fin.sSb;
            const int c = tid - 32;
            if (c < 256) {
                float o = 0.f;
#pragma unroll 16
                for (int e = 0; e < Ex; e++) o += ts.fin.sB[e] * Wv[e * Ex + c];
                out[OFF_BC + b * Ex + c] = o * invSb;
            }
        }
        __syncthreads();

        // ---- phase D: weights + gather ----
        if (tid < NAx) {
            const int sel = ts.fin.s_sel[tid];
            const float l = mono2f(ts.fin.s_uv[tid]);
            const float mk = mask[(size_t)b * Nx + sel];
            const float mm = (mk == -2.f) ? 0.f : 1.f;
            const float wgt = __expf(l) / ts.fin.sSb * mm;
            out[OFF_INDS + b * NAx + tid] = (float)sel;
            out[OFF_W    + b * NAx + tid] = wgt;
            g_wt[b * NAx + tid] = wgt;
        }
        __syncthreads();

        if (tid < 256) {
            const float inv_dnm = 1.f / powf(40.f, (float)tid * (1.f / 256.f));
#pragma unroll
            for (int a = 0; a < NAx; a++) {
                const int ind = ts.fin.s_sel[a];
                const float xv  = x[((size_t)b * Nx + ind) * Ex + tid];
                const float pos = sinf((float)ind * inv_dnm);
                g_xa[((size_t)b * NAx + a) * Ex + tid] = xv + pos;
            }
        }

        // ---- publish ----
        __threadfence();
        __syncthreads();
        if (tid == 0) atomicExch(&g_flag[b], 1);

    } else {
        // ================= ANCHOR ROLE =================
        const int idx = blockIdx.x - 32;     // 0..127
        const int bg  = idx & 7;             // batch group
        const int a   = idx >> 3;            // anchor
        const int b0  = bg * 4;
        const int t   = tid;

        const int half = t >> 8;             // 0: w matrix, 1: g matrix
        const int fg   = t & 63;             // f-group: f = fg*4 .. fg*4+3
        const int ec   = (t >> 6) & 3;       // e-chunk: e = ec*64 .. ec*64+63

        // stripe-prefetch w/g into L2 (overlaps the finish blocks)
        {
            const float4* wp4 = (const float4*)wmat + (size_t)idx * 2048;
            const float4* gp4 = (const float4*)gmat + (size_t)idx * 2048;
            float sink = 0.f;
#pragma unroll
            for (int i = 0; i < 4; i++) {
                const float4 pa = __ldg(wp4 + t + i * 512);
                const float4 pb = __ldg(gp4 + t + i * 512);
                sink += pa.x + pa.y + pa.z + pa.w + pb.x + pb.y + pb.z + pb.w;
            }
            if (__float_as_uint(sink) == 0xdeadbeefu) g_sinkf = sink;  // never taken
        }

        // wait for the 4 producer batches
        if (t == 0) {
#pragma unroll
            for (int i = 0; i < 4; i++)
                while (atomicAdd(&g_flag[b0 + i], 0) == 0) { __nanosleep(64); }
            __threadfence();
        }
        __syncthreads();

        for (int i = t; i < Ex * 4; i += 512) {
            const int e = i >> 2, bs = i & 3;
            ts.anc.xs[i] = __ldcg(&g_xa[((size_t)(b0 + bs) * NAx + a) * Ex + e]);
        }
        if (t < 4) ts.anc.wts[t] = __ldcg(&g_wt[(b0 + t) * NAx + a]);
        __syncthreads();

        unsigned long long acc[8];
#pragma unroll
        for (int j = 0; j < 8; j++) acc[j] = 0ull;

        const float4* m4 = (const float4*)((half ? gmat : wmat) + (size_t)a * Ex * Ex);
        const int e0 = ec * 64;
#pragma unroll 16
        for (int e2 = 0; e2 < 64; e2++) {
            const int e = e0 + e2;
            const float4 mv = m4[e * 64 + fg];
            const unsigned long long xp0 = *(const unsigned long long*)&ts.anc.xs[e * 4];
            const unsigned long long xp1 = *(const unsigned long long*)&ts.anc.xs[e * 4 + 2];
            unsigned long long d0, d1, d2, d3;
            DUP2(d0, __float_as_uint(mv.x));
            DUP2(d1, __float_as_uint(mv.y));
            DUP2(d2, __float_as_uint(mv.z));
            DUP2(d3, __float_as_uint(mv.w));
            FMA2(acc[0], xp0, d0);  FMA2(acc[1], xp1, d0);
            FMA2(acc[2], xp0, d1);  FMA2(acc[3], xp1, d1);
            FMA2(acc[4], xp0, d2);  FMA2(acc[5], xp1, d2);
            FMA2(acc[6], xp0, d3);  FMA2(acc[7], xp1, d3);
        }

        {
            unsigned long long* dst = &ts.anc.spd[(((half << 6) | fg) * 4 + ec) * 8];
#pragma unroll
            for (int j = 0; j < 8; j++) dst[j] = acc[j];
        }
        __syncthreads();

        const int f = t & 255;
        float aw[4], ag[4], pre[4];
        if (t < 256) {
            const int fg2 = f >> 2, fi = f & 3;
#pragma unroll
            for (int h = 0; h < 2; h++) {
#pragma unroll
                for (int pr = 0; pr < 2; pr++) {
                    const unsigned long long* src =
                        &ts.anc.spd[((h << 6) | fg2) * 4 * 8 + fi * 2 + pr];
                    unsigned long long s = src[0];
                    ADD2(s, src[8]);
                    ADD2(s, src[16]);
                    ADD2(s, src[24]);
                    const float lo2 = __uint_as_float((unsigned)(s & 0xFFFFFFFFull));
                    const float hi2 = __uint_as_float((unsigned)(s >> 32));
                    if (h == 0) { aw[pr * 2] = lo2; aw[pr * 2 + 1] = hi2; }
                    else        { ag[pr * 2] = lo2; ag[pr * 2 + 1] = hi2; }
                }
            }
#pragma unroll
            for (int bs = 0; bs < 4; bs++)
                pre[bs] = aw[bs] / (1.f + __expf(-ag[bs])) * ts.anc.wts[bs];
#pragma unroll
            for (int bs = 0; bs < 4; bs++) {
                float s1 = pre[bs], s2 = pre[bs] * pre[bs];
#pragma unroll
                for (int off = 16; off; off >>= 1) {
                    s1 += __shfl_xor_sync(0xffffffffu, s1, off);
                    s2 += __shfl_xor_sync(0xffffffffu, s2, off);
                }
                if (lane == 0) { ts.anc.rsum[warp][bs] = s1; ts.anc.rsq[warp][bs] = s2; }
            }
        }
        __syncthreads();

        if (t < 256) {
            const float gam = gamma[f], bet = beta[f];
#pragma unroll
            for (int bs = 0; bs < 4; bs++) {
                float S = 0.f, Q = 0.f;
#pragma unroll
                for (int w2 = 0; w2 < 8; w2++) { S += ts.anc.rsum[w2][bs]; Q += ts.anc.rsq[w2][bs]; }
                const float mu  = S * (1.f / 256.f);
                const float var = Q * (1.f / 256.f) - mu * mu;
                out[((size_t)(b0 + bs) * NAx + a) * Ex + f] =
                    (pre[bs] - mu) * rsqrtf(var + 0.001f) * gam + bet;
            }
        }
    }
}

// ------------------------------------------------------------------
extern "C" void kernel_launch(void* const* d_in, const int* in_sizes, int n_in,
                              void* d_out, int out_size) {
    const float* x       = (const float*)d_in[0];
    const float* mask    = (const float*)d_in[1];
    const float* barcode = (const float*)d_in[2];
    const float* Wq      = (const float*)d_in[3];
    const float* Wk      = (const float*)d_in[4];
    const float* Wv      = (const float*)d_in[5];
    const float* g       = (const float*)d_in[6];
    const float* w       = (const float*)d_in[7];
    const float* ln_g    = (const float*)d_in[8];
    const float* ln_b    = (const float*)d_in[9];
    float* out = (float*)d_out;

    k_prep1<<<64, 256>>>(barcode, Wq);
    k_prep2<<<32, 256>>>(Wk);
    k_pass1<<<dim3(Nx / 256, Bx), 256>>>(x, mask);
    k_tail<<<160, 512>>>(x, mask, Wv, w, g, ln_g, ln_b, out);
}